// round 10
// baseline (speedup 1.0000x reference)
#include <cuda_runtime.h>
#include <cuda_fp16.h>
#include <math.h>
#include <stdint.h>

#define NB 16
#define NN 1024

// ---------------- helpers ----------------
__device__ __forceinline__ uint32_t smem_to_u32(const void* p) {
    uint32_t a;
    asm("{ .reg .u64 t; cvta.to.shared.u64 t, %1; cvt.u32.u64 %0, t; }" : "=r"(a) : "l"(p));
    return a;
}
__device__ __forceinline__ void cp16(uint32_t dst, const void* src) {
    asm volatile("cp.async.cg.shared.global [%0], [%1], 16;" :: "r"(dst), "l"(src));
}
__device__ __forceinline__ void cp_commit() { asm volatile("cp.async.commit_group;" ::: "memory"); }
__device__ __forceinline__ void cp_wait0()  { asm volatile("cp.async.wait_group 0;" ::: "memory"); }

__device__ __forceinline__ void ldsm4(uint32_t* r, uint32_t addr) {
    asm volatile("ldmatrix.sync.aligned.m8n8.x4.shared.b16 {%0,%1,%2,%3}, [%4];"
                 : "=r"(r[0]), "=r"(r[1]), "=r"(r[2]), "=r"(r[3]) : "r"(addr));
}
__device__ __forceinline__ void mma_fp16(float* c, const uint32_t* a, const uint32_t* b) {
    asm volatile(
        "mma.sync.aligned.m16n8k16.row.col.f32.f16.f16.f32 "
        "{%0,%1,%2,%3}, {%4,%5,%6,%7}, {%8,%9}, {%0,%1,%2,%3};"
        : "+f"(c[0]), "+f"(c[1]), "+f"(c[2]), "+f"(c[3])
        : "r"(a[0]), "r"(a[1]), "r"(a[2]), "r"(a[3]), "r"(b[0]), "r"(b[1]));
}

// ---------------- scratch (device globals) ----------------
#define TOT ((size_t)NB * NN * NN)
__device__ __half g_f1h[TOT], g_f1l[TOT];
__device__ __half g_f2h[TOT], g_f2l[TOT];
__device__ __half g_wth[NN * NN], g_wtl[NN * NN];
__device__ __half g_a1h[TOT], g_a1l[TOT];
__device__ __half g_et[TOT];               // E_T (single fp16)
__device__ __half g_er[TOT];               // E_r (single fp16)
__device__ float g_cc[TOT];
__device__ float g_pmax[NB * 8 * NN];
__device__ float g_psum[NB * 8 * NN];
__device__ float g_mc[NB * NN], g_invc[NB * NN], g_invr[NB * NN];

// ---------------- fp16 GEMM body (R8 proven layout) ----------------
// C[M,N] = A[M,K] · B[N,K]^T.
// Products: hh always; +hl if B_SPLIT; +lh if A_SPLIT.
// 256 threads, 8 warps (2m x 4n), 128x128 tile, warp tile 64x32, BK=32,
// 2-stage cp.async, 2 CTAs/SM.
#define BK 32
#define ROWB 80                         // bytes per smem row (64 data + 16 pad)
#define AH_OFF 0
#define AL_OFF (128 * ROWB)             // 10240
#define BH_OFF (2 * 128 * ROWB)         // 20480
#define BL_OFF (3 * 128 * ROWB)         // 30720
#define SLOTB (4 * 128 * ROWB)          // 40960
#define SMEM_DYN (2 * SLOTB)            // 81920 -> 2 CTAs/SM
#define KT 32

template<bool A_SPLIT, bool B_SPLIT, bool SPLIT_OUT, bool SCALE>
__device__ __forceinline__ void gemm_body(
    const __half* __restrict__ Ah, const __half* __restrict__ Al,
    const __half* __restrict__ Bh, const __half* __restrict__ Bl,
    float* __restrict__ C, __half* __restrict__ Ch, __half* __restrict__ Cl,
    const float* __restrict__ scb, char* dsm)
{
    const uint32_t sb = smem_to_u32(dsm);
    const int tid = threadIdx.x;
    const int lane = tid & 31;
    const int w = tid >> 5;
    const int wm = w & 1;        // 2 m groups of 64 rows
    const int wn = w >> 1;       // 4 n groups of 32 cols
    const int m0 = blockIdx.y * 128;
    const int n0 = blockIdx.x * 128;

    float acc[4][4][4];
    #pragma unroll
    for (int i = 0; i < 4; i++)
        #pragma unroll
        for (int j = 0; j < 4; j++)
            #pragma unroll
            for (int q = 0; q < 4; q++) acc[i][j][q] = 0.0f;

    auto load_stage = [&](int slot, int kt) {
        uint32_t base = sb + slot * SLOTB;
        int k0 = kt * BK;
        #pragma unroll
        for (int i = 0; i < 2; i++) {
            int f = tid + i * 256;
            int row = f >> 2, ch = f & 3;
            uint32_t so = row * ROWB + ch * 16;
            size_t gA = ((size_t)(m0 + row) << 10) + k0 + ch * 8;
            size_t gB = ((size_t)(n0 + row) << 10) + k0 + ch * 8;
            cp16(base + AH_OFF + so, Ah + gA);
            if (A_SPLIT) cp16(base + AL_OFF + so, Al + gA);
            cp16(base + BH_OFF + so, Bh + gB);
            if (B_SPLIT) cp16(base + BL_OFF + so, Bl + gB);
        }
        cp_commit();
    };

    load_stage(0, 0);

    const int arow = wm * 64 + (lane & 15);                      // + mt*16
    const int achk = lane >> 4;                                  // + 2*ks
    const int brow = wn * 32 + ((lane & 16) >> 1) + (lane & 7);  // + p*16
    const int bchk = (lane >> 3) & 1;                            // + 2*ks

    for (int kt = 0; kt < KT; kt++) {
        cp_wait0();
        __syncthreads();
        if (kt + 1 < KT) load_stage((kt + 1) & 1, kt + 1);

        uint32_t sa = sb + (kt & 1) * SLOTB;
        #pragma unroll
        for (int ks = 0; ks < 2; ks++) {
            uint32_t a_h[4][4], a_l[4][4], b_h[2][4], b_l[2][4];
            #pragma unroll
            for (int mt = 0; mt < 4; mt++) {
                uint32_t ad = sa + AH_OFF + (arow + mt * 16) * ROWB + (ks * 2 + achk) * 16;
                ldsm4(a_h[mt], ad);
                if (A_SPLIT) ldsm4(a_l[mt], ad + (AL_OFF - AH_OFF));
            }
            #pragma unroll
            for (int p = 0; p < 2; p++) {
                uint32_t bd = sa + BH_OFF + (brow + p * 16) * ROWB + (ks * 2 + bchk) * 16;
                ldsm4(b_h[p], bd);
                if (B_SPLIT) ldsm4(b_l[p], bd + (BL_OFF - BH_OFF));
            }
            // product-major passes: 16 independent accumulators per pass
            #pragma unroll
            for (int mt = 0; mt < 4; mt++)
                #pragma unroll
                for (int nt = 0; nt < 4; nt++)
                    mma_fp16(acc[mt][nt], a_h[mt], &b_h[nt >> 1][(nt & 1) * 2]);
            if (B_SPLIT) {
                #pragma unroll
                for (int mt = 0; mt < 4; mt++)
                    #pragma unroll
                    for (int nt = 0; nt < 4; nt++)
                        mma_fp16(acc[mt][nt], a_h[mt], &b_l[nt >> 1][(nt & 1) * 2]);
            }
            if (A_SPLIT) {
                #pragma unroll
                for (int mt = 0; mt < 4; mt++)
                    #pragma unroll
                    for (int nt = 0; nt < 4; nt++)
                        mma_fp16(acc[mt][nt], a_l[mt], &b_h[nt >> 1][(nt & 1) * 2]);
            }
        }
    }

    // ---- epilogue ----
    #pragma unroll
    for (int mt = 0; mt < 4; mt++) {
        int mr = m0 + wm * 64 + mt * 16 + (lane >> 2);
        float s0 = 1.0f, s1 = 1.0f;
        if (SCALE) {
            s0 = scb[mr];
            s1 = scb[mr + 8];
        }
        #pragma unroll
        for (int nt = 0; nt < 4; nt++) {
            int nc = n0 + wn * 32 + nt * 8 + (lane & 3) * 2;
            size_t i0 = ((size_t)mr << 10) + nc;
            size_t i1 = i0 + (8 << 10);
            float v00 = acc[mt][nt][0] * s0, v01 = acc[mt][nt][1] * s0;
            float v10 = acc[mt][nt][2] * s1, v11 = acc[mt][nt][3] * s1;
            if (SPLIT_OUT) {
                __half h00 = __float2half_rn(v00), h01 = __float2half_rn(v01);
                __half h10 = __float2half_rn(v10), h11 = __float2half_rn(v11);
                *(__half2*)(Ch + i0) = __halves2half2(h00, h01);
                *(__half2*)(Ch + i1) = __halves2half2(h10, h11);
                *(__half2*)(Cl + i0) = __halves2half2(
                    __float2half_rn(v00 - __half2float(h00)),
                    __float2half_rn(v01 - __half2float(h01)));
                *(__half2*)(Cl + i1) = __halves2half2(
                    __float2half_rn(v10 - __half2float(h10)),
                    __float2half_rn(v11 - __half2float(h11)));
            } else {
                *(float2*)(C + i0) = make_float2(v00, v01);
                *(float2*)(C + i1) = make_float2(v10, v11);
            }
        }
    }
}

template<bool A_SPLIT, bool B_SPLIT, bool SPLIT_OUT, bool SCALE>
__global__ __launch_bounds__(256, 2)
void gemm_kernel(const __half* __restrict__ Ah, const __half* __restrict__ Al,
                 const __half* __restrict__ Bh, const __half* __restrict__ Bl,
                 float* __restrict__ C, __half* __restrict__ Ch, __half* __restrict__ Cl,
                 const float* __restrict__ scaleg, size_t sA, size_t sB, size_t sC)
{
    extern __shared__ char dsm[];
    const size_t b = blockIdx.z;
    gemm_body<A_SPLIT, B_SPLIT, SPLIT_OUT, SCALE>(
        Ah + b * sA, A_SPLIT ? Al + b * sA : nullptr,
        Bh + b * sB, B_SPLIT ? Bl + b * sB : nullptr,
        SPLIT_OUT ? nullptr : C + b * sC,
        SPLIT_OUT ? Ch + b * sC : nullptr,
        SPLIT_OUT ? Cl + b * sC : nullptr,
        SCALE ? scaleg + b * NN : nullptr, dsm);
}

// fused attention GEMMs, single-product (Eh·fh):
// z<16 -> out1 = diag(invc)·E_T·f1^T ; z>=16 -> out2 = diag(invr)·E_r·f2^T
__global__ __launch_bounds__(256, 2)
void gemm34_kernel(const __half* __restrict__ A3, const __half* __restrict__ B3,
                   const float* __restrict__ sc3, float* __restrict__ C3,
                   const __half* __restrict__ A4, const __half* __restrict__ B4,
                   const float* __restrict__ sc4, float* __restrict__ C4)
{
    extern __shared__ char dsm[];
    const int z = blockIdx.z;
    const size_t off = (size_t)(z & 15) << 20;
    const int bn = (z & 15) * NN;
    if (z < 16)
        gemm_body<false, false, false, true>(A3 + off, nullptr, B3 + off, nullptr,
                                             C3 + off, nullptr, nullptr, sc3 + bn, dsm);
    else
        gemm_body<false, false, false, true>(A4 + off, nullptr, B4 + off, nullptr,
                                             C4 + off, nullptr, nullptr, sc4 + bn, dsm);
}

// ---------------- elementwise / reduction kernels ----------------
__global__ void split_kernel(const float* __restrict__ x, __half* __restrict__ h,
                             __half* __restrict__ l)
{
    size_t i = ((size_t)blockIdx.x * 256 + threadIdx.x) * 4;
    float4 v = *(const float4*)(x + i);
    union { __half hh[4]; uint2 u; } ph, pl;
    float f[4] = {v.x, v.y, v.z, v.w};
    #pragma unroll
    for (int j = 0; j < 4; j++) {
        __half b = __float2half_rn(f[j]);
        ph.hh[j] = b;
        pl.hh[j] = __float2half_rn(f[j] - __half2float(b));
    }
    *(uint2*)(h + i) = ph.u;
    *(uint2*)(l + i) = pl.u;
}

__global__ void wtrans_kernel(const float* __restrict__ W, __half* __restrict__ h,
                              __half* __restrict__ l)
{
    __shared__ float tile[32][33];
    int e0 = blockIdx.x << 5, d0 = blockIdx.y << 5;
    int tx = threadIdx.x, ty = threadIdx.y;
    #pragma unroll
    for (int j = 0; j < 4; j++) {
        int r = ty + (j << 3);
        tile[r][tx] = W[(size_t)(d0 + r) * NN + e0 + tx];
    }
    __syncthreads();
    #pragma unroll
    for (int j = 0; j < 4; j++) {
        int r = ty + (j << 3);
        float v = tile[tx][r];                      // W[d0+tx][e0+r]
        __half hh = __float2half_rn(v);
        size_t o = (size_t)(e0 + r) * NN + d0 + tx; // WT[e][d]
        h[o] = hh;
        l[o] = __float2half_rn(v - __half2float(hh));
    }
}

__global__ void pmax_kernel(const float* __restrict__ cc, float* __restrict__ pm)
{
    int b = blockIdx.z, sc = blockIdx.y;
    int t = blockIdx.x * 256 + threadIdx.x;
    const float* p = cc + ((size_t)b << 20) + ((size_t)sc << 17) + t;
    float m = -INFINITY;
    #pragma unroll 8
    for (int s = 0; s < 128; s++) m = fmaxf(m, p[(size_t)s << 10]);
    pm[((b << 3) + sc) * NN + t] = m;
}

__global__ void psum_kernel(const float* __restrict__ cc, const float* __restrict__ pm,
                            float* __restrict__ ps, float* __restrict__ mc)
{
    int b = blockIdx.z, sc = blockIdx.y;
    int t = blockIdx.x * 256 + threadIdx.x;
    float m = -INFINITY;
    #pragma unroll
    for (int c = 0; c < 8; c++) m = fmaxf(m, pm[((b << 3) + c) * NN + t]);
    if (sc == 0) mc[b * NN + t] = m;
    const float* p = cc + ((size_t)b << 20) + ((size_t)sc << 17) + t;
    float sum = 0.0f;
    #pragma unroll 4
    for (int s = 0; s < 128; s++) sum += expf(p[(size_t)s << 10] - m);
    ps[((b << 3) + sc) * NN + t] = sum;
}
__global__ void sumred_kernel(const float* __restrict__ ps, float* __restrict__ invc)
{
    int b = blockIdx.y;
    int t = blockIdx.x * 256 + threadIdx.x;
    float s = 0.0f;
    #pragma unroll
    for (int c = 0; c < 8; c++) s += ps[((b << 3) + c) * NN + t];
    invc[b * NN + t] = 1.0f / s;
}

// E_T[t][s] = exp(cc[s][t] - mc[t]) as fp16 (transposed write)
__global__ void expT_kernel(const float* __restrict__ cc, const float* __restrict__ mc,
                            __half* __restrict__ E)
{
    __shared__ float tile[32][33];
    int b = blockIdx.z;
    int s0 = blockIdx.x << 5, t0 = blockIdx.y << 5;
    int tx = threadIdx.x, ty = threadIdx.y;
    size_t cb = (size_t)b << 20;
    #pragma unroll
    for (int j = 0; j < 4; j++) {
        int r = ty + (j << 3);
        tile[r][tx] = cc[cb + ((size_t)(s0 + r) << 10) + t0 + tx];
    }
    __syncthreads();
    #pragma unroll
    for (int j = 0; j < 4; j++) {
        int r = ty + (j << 3);
        float m = mc[b * NN + t0 + r];
        float e = expf(tile[tx][r] - m);
        E[cb + ((size_t)(t0 + r) << 10) + s0 + tx] = __float2half_rn(e);
    }
}

// row softmax: E_r (fp16) + invr
__global__ void exprow_kernel(const float* __restrict__ cc, __half* __restrict__ E,
                              float* __restrict__ invr)
{
    __shared__ float red[256];
    int b = blockIdx.y, s = blockIdx.x;
    size_t base = ((size_t)b << 20) + ((size_t)s << 10);
    int t0 = threadIdx.x * 4;
    float4 q = *(const float4*)(cc + base + t0);
    float m = fmaxf(fmaxf(q.x, q.y), fmaxf(q.z, q.w));
    red[threadIdx.x] = m;
    __syncthreads();
    #pragma unroll
    for (int o = 128; o > 0; o >>= 1) {
        if (threadIdx.x < o) red[threadIdx.x] = fmaxf(red[threadIdx.x], red[threadIdx.x + o]);
        __syncthreads();
    }
    m = red[0];
    __syncthreads();
    float e[4] = {expf(q.x - m), expf(q.y - m), expf(q.z - m), expf(q.w - m)};
    union { __half h[4]; uint2 u; } ph;
    #pragma unroll
    for (int j = 0; j < 4; j++) ph.h[j] = __float2half_rn(e[j]);
    *(uint2*)(E + base + t0) = ph.u;
    red[threadIdx.x] = e[0] + e[1] + e[2] + e[3];
    __syncthreads();
    #pragma unroll
    for (int o = 128; o > 0; o >>= 1) {
        if (threadIdx.x < o) red[threadIdx.x] += red[threadIdx.x + o];
        __syncthreads();
    }
    if (threadIdx.x == 0) invr[b * NN + s] = 1.0f / red[0];
}

// ---------------- host ----------------
extern "C" void kernel_launch(void* const* d_in, const int* in_sizes, int n_in,
                              void* d_out, int out_size)
{
    const float* f1 = (const float*)d_in[0];
    const float* f2 = (const float*)d_in[1];
    const float* W  = (const float*)d_in[2];
    float* out1 = (float*)d_out;
    float* out2 = out1 + ((size_t)NB << 20);

    __half *f1h, *f1l, *f2h, *f2l, *wth, *wtl, *a1h, *a1l, *et, *er;
    float *cc, *pm, *ps, *mc, *invc, *invr;
    cudaGetSymbolAddress((void**)&f1h, g_f1h); cudaGetSymbolAddress((void**)&f1l, g_f1l);
    cudaGetSymbolAddress((void**)&f2h, g_f2h); cudaGetSymbolAddress((void**)&f2l, g_f2l);
    cudaGetSymbolAddress((void**)&wth, g_wth); cudaGetSymbolAddress((void**)&wtl, g_wtl);
    cudaGetSymbolAddress((void**)&a1h, g_a1h); cudaGetSymbolAddress((void**)&a1l, g_a1l);
    cudaGetSymbolAddress((void**)&et, g_et);   cudaGetSymbolAddress((void**)&er, g_er);
    cudaGetSymbolAddress((void**)&cc, g_cc);
    cudaGetSymbolAddress((void**)&pm, g_pmax); cudaGetSymbolAddress((void**)&ps, g_psum);
    cudaGetSymbolAddress((void**)&mc, g_mc);   cudaGetSymbolAddress((void**)&invc, g_invc);
    cudaGetSymbolAddress((void**)&invr, g_invr);

    cudaFuncSetAttribute(gemm_kernel<true, true, true,  false>, cudaFuncAttributeMaxDynamicSharedMemorySize, SMEM_DYN);
    cudaFuncSetAttribute(gemm_kernel<true, true, false, false>, cudaFuncAttributeMaxDynamicSharedMemorySize, SMEM_DYN);
    cudaFuncSetAttribute(gemm34_kernel, cudaFuncAttributeMaxDynamicSharedMemorySize, SMEM_DYN);

    const size_t MBe = (size_t)1 << 20;
    dim3 gg(8, 8, NB);       // 128x128 tiles -> 1024 CTAs
    dim3 gg34(8, 8, 2 * NB); // fused attention GEMMs -> 2048 CTAs

    // fp16 splits
    split_kernel<<<16384, 256>>>(f1, f1h, f1l);
    split_kernel<<<16384, 256>>>(f2, f2h, f2l);
    wtrans_kernel<<<dim3(32, 32), dim3(32, 8)>>>(W, wth, wtl);

    // 1. a1 = f1 @ W (3-product) -> fp16 split
    gemm_kernel<true, true, true,  false><<<gg, 256, SMEM_DYN>>>(f1h, f1l, wth, wtl,
                                                                 nullptr, a1h, a1l, nullptr, MBe, 0, MBe);
    // 2. cc = a1 @ f2^T (3-product) -> fp32
    gemm_kernel<true, true, false, false><<<gg, 256, SMEM_DYN>>>(a1h, a1l, f2h, f2l,
                                                                 cc, nullptr, nullptr, nullptr, MBe, MBe, MBe);
    // 3. column softmax stats
    pmax_kernel<<<dim3(4, 8, NB), 256>>>(cc, pm);
    psum_kernel<<<dim3(4, 8, NB), 256>>>(cc, pm, ps, mc);
    sumred_kernel<<<dim3(4, NB), 256>>>(ps, invc);
    // 4. E_T (fp16, transposed)
    expT_kernel<<<dim3(32, 32, NB), dim3(32, 8)>>>(cc, mc, et);
    // 5. row softmax (fp16 E_r + invr)
    exprow_kernel<<<dim3(NN, NB), 256>>>(cc, er, invr);
    // 6. fused attention GEMMs, single product (Eh·fh):
    gemm34_kernel<<<gg34, 256, SMEM_DYN>>>(et, f1h, invc, out1,
                                           er, f2h, invr, out2);
}

// round 11
// speedup vs baseline: 1.5241x; 1.5241x over previous
#include <cuda_runtime.h>
#include <cuda_fp16.h>
#include <math.h>
#include <stdint.h>

#define NB 16
#define NN 1024

// ---------------- helpers ----------------
__device__ __forceinline__ uint32_t smem_to_u32(const void* p) {
    uint32_t a;
    asm("{ .reg .u64 t; cvta.to.shared.u64 t, %1; cvt.u32.u64 %0, t; }" : "=r"(a) : "l"(p));
    return a;
}
__device__ __forceinline__ void cp16(uint32_t dst, const void* src) {
    asm volatile("cp.async.cg.shared.global [%0], [%1], 16;" :: "r"(dst), "l"(src));
}
__device__ __forceinline__ void cp_commit() { asm volatile("cp.async.commit_group;" ::: "memory"); }
__device__ __forceinline__ void cp_wait0()  { asm volatile("cp.async.wait_group 0;" ::: "memory"); }

__device__ __forceinline__ void ldsm4(uint32_t* r, uint32_t addr) {
    asm volatile("ldmatrix.sync.aligned.m8n8.x4.shared.b16 {%0,%1,%2,%3}, [%4];"
                 : "=r"(r[0]), "=r"(r[1]), "=r"(r[2]), "=r"(r[3]) : "r"(addr));
}
__device__ __forceinline__ void mma_fp16(float* c, const uint32_t* a, const uint32_t* b) {
    asm volatile(
        "mma.sync.aligned.m16n8k16.row.col.f32.f16.f16.f32 "
        "{%0,%1,%2,%3}, {%4,%5,%6,%7}, {%8,%9}, {%0,%1,%2,%3};"
        : "+f"(c[0]), "+f"(c[1]), "+f"(c[2]), "+f"(c[3])
        : "r"(a[0]), "r"(a[1]), "r"(a[2]), "r"(a[3]), "r"(b[0]), "r"(b[1]));
}

// ---------------- scratch (device globals) ----------------
#define TOT ((size_t)NB * NN * NN)
__device__ __half g_f1h[TOT], g_f1l[TOT];
__device__ __half g_f2h[TOT], g_f2l[TOT];
__device__ __half g_wth[NN * NN], g_wtl[NN * NN];
__device__ __half g_a1h[TOT], g_a1l[TOT];
__device__ __half g_et[TOT];               // E_T (single fp16)
__device__ __half g_er[TOT];               // E_r (single fp16)
__device__ float g_cc[TOT];
__device__ float g_pmax[NB * 8 * NN];
__device__ float g_psum[NB * 8 * NN];
__device__ float g_mc[NB * NN], g_invc[NB * NN], g_invr[NB * NN];

// ---------------- fp16 GEMM body (R8 proven layout) ----------------
// C[M,N] = A[M,K] · B[N,K]^T.
// Products: hh always; +hl if B_SPLIT; +lh if A_SPLIT.
// 256 threads, 8 warps (2m x 4n), 128x128 tile, warp tile 64x32, BK=32,
// 2-stage cp.async, 2 CTAs/SM.
#define BK 32
#define ROWB 80                         // bytes per smem row (64 data + 16 pad)
#define AH_OFF 0
#define AL_OFF (128 * ROWB)             // 10240
#define BH_OFF (2 * 128 * ROWB)         // 20480
#define BL_OFF (3 * 128 * ROWB)         // 30720
#define SLOTB (4 * 128 * ROWB)          // 40960
#define SMEM_DYN (2 * SLOTB)            // 81920 -> 2 CTAs/SM
#define KT 32

template<bool A_SPLIT, bool B_SPLIT, bool SPLIT_OUT, bool SCALE>
__device__ __forceinline__ void gemm_body(
    const __half* __restrict__ Ah, const __half* __restrict__ Al,
    const __half* __restrict__ Bh, const __half* __restrict__ Bl,
    float* __restrict__ C, __half* __restrict__ Ch, __half* __restrict__ Cl,
    const float* __restrict__ scb, char* dsm)
{
    const uint32_t sb = smem_to_u32(dsm);
    const int tid = threadIdx.x;
    const int lane = tid & 31;
    const int w = tid >> 5;
    const int wm = w & 1;        // 2 m groups of 64 rows
    const int wn = w >> 1;       // 4 n groups of 32 cols
    const int m0 = blockIdx.y * 128;
    const int n0 = blockIdx.x * 128;

    float acc[4][4][4];
    #pragma unroll
    for (int i = 0; i < 4; i++)
        #pragma unroll
        for (int j = 0; j < 4; j++)
            #pragma unroll
            for (int q = 0; q < 4; q++) acc[i][j][q] = 0.0f;

    auto load_stage = [&](int slot, int kt) {
        uint32_t base = sb + slot * SLOTB;
        int k0 = kt * BK;
        #pragma unroll
        for (int i = 0; i < 2; i++) {
            int f = tid + i * 256;
            int row = f >> 2, ch = f & 3;
            uint32_t so = row * ROWB + ch * 16;
            size_t gA = ((size_t)(m0 + row) << 10) + k0 + ch * 8;
            size_t gB = ((size_t)(n0 + row) << 10) + k0 + ch * 8;
            cp16(base + AH_OFF + so, Ah + gA);
            if (A_SPLIT) cp16(base + AL_OFF + so, Al + gA);
            cp16(base + BH_OFF + so, Bh + gB);
            if (B_SPLIT) cp16(base + BL_OFF + so, Bl + gB);
        }
        cp_commit();
    };

    load_stage(0, 0);

    const int arow = wm * 64 + (lane & 15);                      // + mt*16
    const int achk = lane >> 4;                                  // + 2*ks
    const int brow = wn * 32 + ((lane & 16) >> 1) + (lane & 7);  // + p*16
    const int bchk = (lane >> 3) & 1;                            // + 2*ks

    for (int kt = 0; kt < KT; kt++) {
        cp_wait0();
        __syncthreads();
        if (kt + 1 < KT) load_stage((kt + 1) & 1, kt + 1);

        uint32_t sa = sb + (kt & 1) * SLOTB;
        #pragma unroll
        for (int ks = 0; ks < 2; ks++) {
            uint32_t a_h[4][4], a_l[4][4], b_h[2][4], b_l[2][4];
            #pragma unroll
            for (int mt = 0; mt < 4; mt++) {
                uint32_t ad = sa + AH_OFF + (arow + mt * 16) * ROWB + (ks * 2 + achk) * 16;
                ldsm4(a_h[mt], ad);
                if (A_SPLIT) ldsm4(a_l[mt], ad + (AL_OFF - AH_OFF));
            }
            #pragma unroll
            for (int p = 0; p < 2; p++) {
                uint32_t bd = sa + BH_OFF + (brow + p * 16) * ROWB + (ks * 2 + bchk) * 16;
                ldsm4(b_h[p], bd);
                if (B_SPLIT) ldsm4(b_l[p], bd + (BL_OFF - BH_OFF));
            }
            // product-major passes: 16 independent accumulators per pass
            #pragma unroll
            for (int mt = 0; mt < 4; mt++)
                #pragma unroll
                for (int nt = 0; nt < 4; nt++)
                    mma_fp16(acc[mt][nt], a_h[mt], &b_h[nt >> 1][(nt & 1) * 2]);
            if (B_SPLIT) {
                #pragma unroll
                for (int mt = 0; mt < 4; mt++)
                    #pragma unroll
                    for (int nt = 0; nt < 4; nt++)
                        mma_fp16(acc[mt][nt], a_h[mt], &b_l[nt >> 1][(nt & 1) * 2]);
            }
            if (A_SPLIT) {
                #pragma unroll
                for (int mt = 0; mt < 4; mt++)
                    #pragma unroll
                    for (int nt = 0; nt < 4; nt++)
                        mma_fp16(acc[mt][nt], a_l[mt], &b_h[nt >> 1][(nt & 1) * 2]);
            }
        }
    }

    // ---- epilogue ----
    #pragma unroll
    for (int mt = 0; mt < 4; mt++) {
        int mr = m0 + wm * 64 + mt * 16 + (lane >> 2);
        float s0 = 1.0f, s1 = 1.0f;
        if (SCALE) {
            s0 = scb[mr];
            s1 = scb[mr + 8];
        }
        #pragma unroll
        for (int nt = 0; nt < 4; nt++) {
            int nc = n0 + wn * 32 + nt * 8 + (lane & 3) * 2;
            size_t i0 = ((size_t)mr << 10) + nc;
            size_t i1 = i0 + (8 << 10);
            float v00 = acc[mt][nt][0] * s0, v01 = acc[mt][nt][1] * s0;
            float v10 = acc[mt][nt][2] * s1, v11 = acc[mt][nt][3] * s1;
            if (SPLIT_OUT) {
                __half h00 = __float2half_rn(v00), h01 = __float2half_rn(v01);
                __half h10 = __float2half_rn(v10), h11 = __float2half_rn(v11);
                *(__half2*)(Ch + i0) = __halves2half2(h00, h01);
                *(__half2*)(Ch + i1) = __halves2half2(h10, h11);
                *(__half2*)(Cl + i0) = __halves2half2(
                    __float2half_rn(v00 - __half2float(h00)),
                    __float2half_rn(v01 - __half2float(h01)));
                *(__half2*)(Cl + i1) = __halves2half2(
                    __float2half_rn(v10 - __half2float(h10)),
                    __float2half_rn(v11 - __half2float(h11)));
            } else {
                *(float2*)(C + i0) = make_float2(v00, v01);
                *(float2*)(C + i1) = make_float2(v10, v11);
            }
        }
    }
}

template<bool A_SPLIT, bool B_SPLIT, bool SPLIT_OUT, bool SCALE>
__global__ __launch_bounds__(256, 2)
void gemm_kernel(const __half* __restrict__ Ah, const __half* __restrict__ Al,
                 const __half* __restrict__ Bh, const __half* __restrict__ Bl,
                 float* __restrict__ C, __half* __restrict__ Ch, __half* __restrict__ Cl,
                 const float* __restrict__ scaleg, size_t sA, size_t sB, size_t sC)
{
    extern __shared__ char dsm[];
    const size_t b = blockIdx.z;
    gemm_body<A_SPLIT, B_SPLIT, SPLIT_OUT, SCALE>(
        Ah + b * sA, A_SPLIT ? Al + b * sA : nullptr,
        Bh + b * sB, B_SPLIT ? Bl + b * sB : nullptr,
        SPLIT_OUT ? nullptr : C + b * sC,
        SPLIT_OUT ? Ch + b * sC : nullptr,
        SPLIT_OUT ? Cl + b * sC : nullptr,
        SCALE ? scaleg + b * NN : nullptr, dsm);
}

// fused attention GEMMs, single-product (Eh·fh):
// z<16 -> out1 = diag(invc)·E_T·f1^T ; z>=16 -> out2 = diag(invr)·E_r·f2^T
__global__ __launch_bounds__(256, 2)
void gemm34_kernel(const __half* __restrict__ A3, const __half* __restrict__ B3,
                   const float* __restrict__ sc3, float* __restrict__ C3,
                   const __half* __restrict__ A4, const __half* __restrict__ B4,
                   const float* __restrict__ sc4, float* __restrict__ C4)
{
    extern __shared__ char dsm[];
    const int z = blockIdx.z;
    const size_t off = (size_t)(z & 15) << 20;
    const int bn = (z & 15) * NN;
    if (z < 16)
        gemm_body<false, false, false, true>(A3 + off, nullptr, B3 + off, nullptr,
                                             C3 + off, nullptr, nullptr, sc3 + bn, dsm);
    else
        gemm_body<false, false, false, true>(A4 + off, nullptr, B4 + off, nullptr,
                                             C4 + off, nullptr, nullptr, sc4 + bn, dsm);
}

// ---------------- elementwise / reduction kernels ----------------
__global__ void split_kernel(const float* __restrict__ x, __half* __restrict__ h,
                             __half* __restrict__ l)
{
    size_t i = ((size_t)blockIdx.x * 256 + threadIdx.x) * 4;
    float4 v = *(const float4*)(x + i);
    union { __half hh[4]; uint2 u; } ph, pl;
    float f[4] = {v.x, v.y, v.z, v.w};
    #pragma unroll
    for (int j = 0; j < 4; j++) {
        __half b = __float2half_rn(f[j]);
        ph.hh[j] = b;
        pl.hh[j] = __float2half_rn(f[j] - __half2float(b));
    }
    *(uint2*)(h + i) = ph.u;
    *(uint2*)(l + i) = pl.u;
}

__global__ void wtrans_kernel(const float* __restrict__ W, __half* __restrict__ h,
                              __half* __restrict__ l)
{
    __shared__ float tile[32][33];
    int e0 = blockIdx.x << 5, d0 = blockIdx.y << 5;
    int tx = threadIdx.x, ty = threadIdx.y;
    #pragma unroll
    for (int j = 0; j < 4; j++) {
        int r = ty + (j << 3);
        tile[r][tx] = W[(size_t)(d0 + r) * NN + e0 + tx];
    }
    __syncthreads();
    #pragma unroll
    for (int j = 0; j < 4; j++) {
        int r = ty + (j << 3);
        float v = tile[tx][r];                      // W[d0+tx][e0+r]
        __half hh = __float2half_rn(v);
        size_t o = (size_t)(e0 + r) * NN + d0 + tx; // WT[e][d]
        h[o] = hh;
        l[o] = __float2half_rn(v - __half2float(hh));
    }
}

__global__ void pmax_kernel(const float* __restrict__ cc, float* __restrict__ pm)
{
    int b = blockIdx.z, sc = blockIdx.y;
    int t = blockIdx.x * 256 + threadIdx.x;
    const float* p = cc + ((size_t)b << 20) + ((size_t)sc << 17) + t;
    float m = -INFINITY;
    #pragma unroll 8
    for (int s = 0; s < 128; s++) m = fmaxf(m, p[(size_t)s << 10]);
    pm[((b << 3) + sc) * NN + t] = m;
}

__global__ void psum_kernel(const float* __restrict__ cc, const float* __restrict__ pm,
                            float* __restrict__ ps, float* __restrict__ mc)
{
    int b = blockIdx.z, sc = blockIdx.y;
    int t = blockIdx.x * 256 + threadIdx.x;
    float m = -INFINITY;
    #pragma unroll
    for (int c = 0; c < 8; c++) m = fmaxf(m, pm[((b << 3) + c) * NN + t]);
    if (sc == 0) mc[b * NN + t] = m;
    const float* p = cc + ((size_t)b << 20) + ((size_t)sc << 17) + t;
    float sum = 0.0f;
    #pragma unroll 4
    for (int s = 0; s < 128; s++) sum += __expf(p[(size_t)s << 10] - m);
    ps[((b << 3) + sc) * NN + t] = sum;
}
__global__ void sumred_kernel(const float* __restrict__ ps, float* __restrict__ invc)
{
    int b = blockIdx.y;
    int t = blockIdx.x * 256 + threadIdx.x;
    float s = 0.0f;
    #pragma unroll
    for (int c = 0; c < 8; c++) s += ps[((b << 3) + c) * NN + t];
    invc[b * NN + t] = 1.0f / s;
}

// E_T[t][s] = exp(cc[s][t] - mc[t]) as fp16 (transposed write)
__global__ void expT_kernel(const float* __restrict__ cc, const float* __restrict__ mc,
                            __half* __restrict__ E)
{
    __shared__ float tile[32][33];
    int b = blockIdx.z;
    int s0 = blockIdx.x << 5, t0 = blockIdx.y << 5;
    int tx = threadIdx.x, ty = threadIdx.y;
    size_t cb = (size_t)b << 20;
    #pragma unroll
    for (int j = 0; j < 4; j++) {
        int r = ty + (j << 3);
        tile[r][tx] = cc[cb + ((size_t)(s0 + r) << 10) + t0 + tx];
    }
    __syncthreads();
    #pragma unroll
    for (int j = 0; j < 4; j++) {
        int r = ty + (j << 3);
        float m = mc[b * NN + t0 + r];
        float e = __expf(tile[tx][r] - m);
        E[cb + ((size_t)(t0 + r) << 10) + s0 + tx] = __float2half_rn(e);
    }
}

// row softmax: E_r (fp16) + invr
__global__ void exprow_kernel(const float* __restrict__ cc, __half* __restrict__ E,
                              float* __restrict__ invr)
{
    __shared__ float red[256];
    int b = blockIdx.y, s = blockIdx.x;
    size_t base = ((size_t)b << 20) + ((size_t)s << 10);
    int t0 = threadIdx.x * 4;
    float4 q = *(const float4*)(cc + base + t0);
    float m = fmaxf(fmaxf(q.x, q.y), fmaxf(q.z, q.w));
    red[threadIdx.x] = m;
    __syncthreads();
    #pragma unroll
    for (int o = 128; o > 0; o >>= 1) {
        if (threadIdx.x < o) red[threadIdx.x] = fmaxf(red[threadIdx.x], red[threadIdx.x + o]);
        __syncthreads();
    }
    m = red[0];
    __syncthreads();
    float e[4] = {__expf(q.x - m), __expf(q.y - m), __expf(q.z - m), __expf(q.w - m)};
    union { __half h[4]; uint2 u; } ph;
    #pragma unroll
    for (int j = 0; j < 4; j++) ph.h[j] = __float2half_rn(e[j]);
    *(uint2*)(E + base + t0) = ph.u;
    red[threadIdx.x] = e[0] + e[1] + e[2] + e[3];
    __syncthreads();
    #pragma unroll
    for (int o = 128; o > 0; o >>= 1) {
        if (threadIdx.x < o) red[threadIdx.x] += red[threadIdx.x + o];
        __syncthreads();
    }
    if (threadIdx.x == 0) invr[b * NN + s] = 1.0f / red[0];
}

// ---------------- host ----------------
extern "C" void kernel_launch(void* const* d_in, const int* in_sizes, int n_in,
                              void* d_out, int out_size)
{
    const float* f1 = (const float*)d_in[0];
    const float* f2 = (const float*)d_in[1];
    const float* W  = (const float*)d_in[2];
    float* out1 = (float*)d_out;
    float* out2 = out1 + ((size_t)NB << 20);

    __half *f1h, *f1l, *f2h, *f2l, *wth, *wtl, *a1h, *a1l, *et, *er;
    float *cc, *pm, *ps, *mc, *invc, *invr;
    cudaGetSymbolAddress((void**)&f1h, g_f1h); cudaGetSymbolAddress((void**)&f1l, g_f1l);
    cudaGetSymbolAddress((void**)&f2h, g_f2h); cudaGetSymbolAddress((void**)&f2l, g_f2l);
    cudaGetSymbolAddress((void**)&wth, g_wth); cudaGetSymbolAddress((void**)&wtl, g_wtl);
    cudaGetSymbolAddress((void**)&a1h, g_a1h); cudaGetSymbolAddress((void**)&a1l, g_a1l);
    cudaGetSymbolAddress((void**)&et, g_et);   cudaGetSymbolAddress((void**)&er, g_er);
    cudaGetSymbolAddress((void**)&cc, g_cc);
    cudaGetSymbolAddress((void**)&pm, g_pmax); cudaGetSymbolAddress((void**)&ps, g_psum);
    cudaGetSymbolAddress((void**)&mc, g_mc);   cudaGetSymbolAddress((void**)&invc, g_invc);
    cudaGetSymbolAddress((void**)&invr, g_invr);

    cudaFuncSetAttribute(gemm_kernel<true, true, true,  false>, cudaFuncAttributeMaxDynamicSharedMemorySize, SMEM_DYN);
    cudaFuncSetAttribute(gemm_kernel<true, true, false, false>, cudaFuncAttributeMaxDynamicSharedMemorySize, SMEM_DYN);
    cudaFuncSetAttribute(gemm34_kernel, cudaFuncAttributeMaxDynamicSharedMemorySize, SMEM_DYN);

    const size_t MBe = (size_t)1 << 20;
    dim3 gg(8, 8, NB);       // 128x128 tiles -> 1024 CTAs
    dim3 gg34(8, 8, 2 * NB); // fused attention GEMMs -> 2048 CTAs

    // fp16 splits
    split_kernel<<<16384, 256>>>(f1, f1h, f1l);
    split_kernel<<<16384, 256>>>(f2, f2h, f2l);
    wtrans_kernel<<<dim3(32, 32), dim3(32, 8)>>>(W, wth, wtl);

    // 1. a1 = f1 @ W (3-product) -> fp16 split
    gemm_kernel<true, true, true,  false><<<gg, 256, SMEM_DYN>>>(f1h, f1l, wth, wtl,
                                                                 nullptr, a1h, a1l, nullptr, MBe, 0, MBe);
    // 2. cc = a1 @ f2^T (3-product) -> fp32
    gemm_kernel<true, true, false, false><<<gg, 256, SMEM_DYN>>>(a1h, a1l, f2h, f2l,
                                                                 cc, nullptr, nullptr, nullptr, MBe, MBe, MBe);
    // 3. column softmax stats
    pmax_kernel<<<dim3(4, 8, NB), 256>>>(cc, pm);
    psum_kernel<<<dim3(4, 8, NB), 256>>>(cc, pm, ps, mc);
    sumred_kernel<<<dim3(4, NB), 256>>>(ps, invc);
    // 4. E_T (fp16, transposed)
    expT_kernel<<<dim3(32, 32, NB), dim3(32, 8)>>>(cc, mc, et);
    // 5. row softmax (fp16 E_r + invr)
    exprow_kernel<<<dim3(NN, NB), 256>>>(cc, er, invr);
    // 6. fused attention GEMMs, single product (Eh·fh)
    gemm34_kernel<<<gg34, 256, SMEM_DYN>>>(et, f1h, invc, out1,
                                           er, f2h, invr, out2);
}

// round 12
// speedup vs baseline: 1.5806x; 1.0370x over previous
#include <cuda_runtime.h>
#include <cuda_fp16.h>
#include <math.h>
#include <stdint.h>

#define NB 16
#define NN 1024

// ---------------- helpers ----------------
__device__ __forceinline__ uint32_t smem_to_u32(const void* p) {
    uint32_t a;
    asm("{ .reg .u64 t; cvta.to.shared.u64 t, %1; cvt.u32.u64 %0, t; }" : "=r"(a) : "l"(p));
    return a;
}
__device__ __forceinline__ void cp16(uint32_t dst, const void* src) {
    asm volatile("cp.async.cg.shared.global [%0], [%1], 16;" :: "r"(dst), "l"(src));
}
__device__ __forceinline__ void cp_commit() { asm volatile("cp.async.commit_group;" ::: "memory"); }
__device__ __forceinline__ void cp_wait0()  { asm volatile("cp.async.wait_group 0;" ::: "memory"); }

__device__ __forceinline__ void ldsm4(uint32_t* r, uint32_t addr) {
    asm volatile("ldmatrix.sync.aligned.m8n8.x4.shared.b16 {%0,%1,%2,%3}, [%4];"
                 : "=r"(r[0]), "=r"(r[1]), "=r"(r[2]), "=r"(r[3]) : "r"(addr));
}
__device__ __forceinline__ void mma_fp16(float* c, const uint32_t* a, const uint32_t* b) {
    asm volatile(
        "mma.sync.aligned.m16n8k16.row.col.f32.f16.f16.f32 "
        "{%0,%1,%2,%3}, {%4,%5,%6,%7}, {%8,%9}, {%0,%1,%2,%3};"
        : "+f"(c[0]), "+f"(c[1]), "+f"(c[2]), "+f"(c[3])
        : "r"(a[0]), "r"(a[1]), "r"(a[2]), "r"(a[3]), "r"(b[0]), "r"(b[1]));
}

// ---------------- scratch (device globals) ----------------
#define TOT ((size_t)NB * NN * NN)
__device__ __half g_f1h[TOT], g_f1l[TOT];
__device__ __half g_f2h[TOT], g_f2l[TOT];
__device__ __half g_wth[NN * NN], g_wtl[NN * NN];
__device__ __half g_a1h[TOT], g_a1l[TOT];
__device__ __half g_et[TOT];               // E_T (single fp16)
__device__ __half g_er[TOT];               // E_r (single fp16)
__device__ float g_cc[TOT];
__device__ float g_pmax[NB * 8 * NN];
__device__ float g_mc[NB * NN], g_invc[NB * NN], g_invr[NB * NN];

// ---------------- fp16 GEMM body (R8/R11 proven layout) for logit GEMMs ----------------
// C[M,N] = A[M,K] · B[N,K]^T, 3 products (hh,hl,lh).
// 256 threads, 8 warps (2m x 4n), 128x128 tile, warp tile 64x32, BK=32,
// 2-stage cp.async, 2 CTAs/SM.
#define BK 32
#define ROWB 80
#define AH_OFF 0
#define AL_OFF (128 * ROWB)
#define BH_OFF (2 * 128 * ROWB)
#define BL_OFF (3 * 128 * ROWB)
#define SLOTB (4 * 128 * ROWB)          // 40960
#define SMEM_DYN (2 * SLOTB)            // 81920 -> 2 CTAs/SM
#define KT 32

template<bool SPLIT_OUT>
__global__ __launch_bounds__(256, 2)
void gemm_kernel(const __half* __restrict__ Ahg, const __half* __restrict__ Alg,
                 const __half* __restrict__ Bhg, const __half* __restrict__ Blg,
                 float* __restrict__ Cg, __half* __restrict__ Chg, __half* __restrict__ Clg,
                 size_t sA, size_t sB, size_t sC)
{
    extern __shared__ char dsm[];
    const uint32_t sb = smem_to_u32(dsm);
    const size_t bz = blockIdx.z;
    const __half* Ah = Ahg + bz * sA;
    const __half* Al = Alg + bz * sA;
    const __half* Bh = Bhg + bz * sB;
    const __half* Bl = Blg + bz * sB;

    const int tid = threadIdx.x;
    const int lane = tid & 31;
    const int w = tid >> 5;
    const int wm = w & 1;
    const int wn = w >> 1;
    const int m0 = blockIdx.y * 128;
    const int n0 = blockIdx.x * 128;

    float acc[4][4][4];
    #pragma unroll
    for (int i = 0; i < 4; i++)
        #pragma unroll
        for (int j = 0; j < 4; j++)
            #pragma unroll
            for (int q = 0; q < 4; q++) acc[i][j][q] = 0.0f;

    auto load_stage = [&](int slot, int kt) {
        uint32_t base = sb + slot * SLOTB;
        int k0 = kt * BK;
        #pragma unroll
        for (int i = 0; i < 2; i++) {
            int f = tid + i * 256;
            int row = f >> 2, ch = f & 3;
            uint32_t so = row * ROWB + ch * 16;
            size_t gA = ((size_t)(m0 + row) << 10) + k0 + ch * 8;
            size_t gB = ((size_t)(n0 + row) << 10) + k0 + ch * 8;
            cp16(base + AH_OFF + so, Ah + gA);
            cp16(base + AL_OFF + so, Al + gA);
            cp16(base + BH_OFF + so, Bh + gB);
            cp16(base + BL_OFF + so, Bl + gB);
        }
        cp_commit();
    };

    load_stage(0, 0);

    const int arow = wm * 64 + (lane & 15);
    const int achk = lane >> 4;
    const int brow = wn * 32 + ((lane & 16) >> 1) + (lane & 7);
    const int bchk = (lane >> 3) & 1;

    for (int kt = 0; kt < KT; kt++) {
        cp_wait0();
        __syncthreads();
        if (kt + 1 < KT) load_stage((kt + 1) & 1, kt + 1);

        uint32_t sa = sb + (kt & 1) * SLOTB;
        #pragma unroll
        for (int ks = 0; ks < 2; ks++) {
            uint32_t a_h[4][4], a_l[4][4], b_h[2][4], b_l[2][4];
            #pragma unroll
            for (int mt = 0; mt < 4; mt++) {
                uint32_t ad = sa + AH_OFF + (arow + mt * 16) * ROWB + (ks * 2 + achk) * 16;
                ldsm4(a_h[mt], ad);
                ldsm4(a_l[mt], ad + (AL_OFF - AH_OFF));
            }
            #pragma unroll
            for (int p = 0; p < 2; p++) {
                uint32_t bd = sa + BH_OFF + (brow + p * 16) * ROWB + (ks * 2 + bchk) * 16;
                ldsm4(b_h[p], bd);
                ldsm4(b_l[p], bd + (BL_OFF - BH_OFF));
            }
            #pragma unroll
            for (int mt = 0; mt < 4; mt++)
                #pragma unroll
                for (int nt = 0; nt < 4; nt++)
                    mma_fp16(acc[mt][nt], a_h[mt], &b_h[nt >> 1][(nt & 1) * 2]);
            #pragma unroll
            for (int mt = 0; mt < 4; mt++)
                #pragma unroll
                for (int nt = 0; nt < 4; nt++)
                    mma_fp16(acc[mt][nt], a_h[mt], &b_l[nt >> 1][(nt & 1) * 2]);
            #pragma unroll
            for (int mt = 0; mt < 4; mt++)
                #pragma unroll
                for (int nt = 0; nt < 4; nt++)
                    mma_fp16(acc[mt][nt], a_l[mt], &b_h[nt >> 1][(nt & 1) * 2]);
        }
    }

    #pragma unroll
    for (int mt = 0; mt < 4; mt++) {
        int mr = m0 + wm * 64 + mt * 16 + (lane >> 2);
        #pragma unroll
        for (int nt = 0; nt < 4; nt++) {
            int nc = n0 + wn * 32 + nt * 8 + (lane & 3) * 2;
            size_t i0 = bz * sC + ((size_t)mr << 10) + nc;
            size_t i1 = i0 + (8 << 10);
            float v00 = acc[mt][nt][0], v01 = acc[mt][nt][1];
            float v10 = acc[mt][nt][2], v11 = acc[mt][nt][3];
            if (SPLIT_OUT) {
                __half h00 = __float2half_rn(v00), h01 = __float2half_rn(v01);
                __half h10 = __float2half_rn(v10), h11 = __float2half_rn(v11);
                *(__half2*)(Chg + i0) = __halves2half2(h00, h01);
                *(__half2*)(Chg + i1) = __halves2half2(h10, h11);
                *(__half2*)(Clg + i0) = __halves2half2(
                    __float2half_rn(v00 - __half2float(h00)),
                    __float2half_rn(v01 - __half2float(h01)));
                *(__half2*)(Clg + i1) = __halves2half2(
                    __float2half_rn(v10 - __half2float(h10)),
                    __float2half_rn(v11 - __half2float(h11)));
            } else {
                *(float2*)(Cg + i0) = make_float2(v00, v01);
                *(float2*)(Cg + i1) = make_float2(v10, v11);
            }
        }
    }
}

// ---------------- single-product attention GEMM, BK=64 ----------------
// C[M,N] = diag(scale) · A[M,K] · B[N,K]^T, single fp16 product.
// 256 threads, 8 warps (2m x 4n), 128x128 tile, warp tile 64x32, BK=64,
// 2 smem arrays, 2-stage, 2 CTAs/SM (73.7KB/CTA), 16 kt -> half the barriers.
#define ROWB64 144                       // 128 data + 16 pad (9x16B slots, odd -> conflict-free)
#define A34_OFF 0
#define B34_OFF (128 * ROWB64)           // 18432
#define SLOT34 (2 * 128 * ROWB64)        // 36864
#define SMEM34 (2 * SLOT34)              // 73728
#define KT34 16

__global__ __launch_bounds__(256, 2)
void gemm34_kernel(const __half* __restrict__ A3, const __half* __restrict__ B3,
                   const float* __restrict__ sc3, float* __restrict__ C3,
                   const __half* __restrict__ A4, const __half* __restrict__ B4,
                   const float* __restrict__ sc4, float* __restrict__ C4)
{
    extern __shared__ char dsm[];
    const uint32_t sb = smem_to_u32(dsm);
    const int z = blockIdx.z;
    const size_t off = (size_t)(z & 15) << 20;
    const int bn = (z & 15) * NN;
    const __half* A = (z < 16) ? A3 + off : A4 + off;
    const __half* B = (z < 16) ? B3 + off : B4 + off;
    const float* scb = ((z < 16) ? sc3 : sc4) + bn;
    float* C = ((z < 16) ? C3 : C4) + off;

    const int tid = threadIdx.x;
    const int lane = tid & 31;
    const int w = tid >> 5;
    const int wm = w & 1;
    const int wn = w >> 1;
    const int m0 = blockIdx.y * 128;
    const int n0 = blockIdx.x * 128;

    float acc[4][4][4];
    #pragma unroll
    for (int i = 0; i < 4; i++)
        #pragma unroll
        for (int j = 0; j < 4; j++)
            #pragma unroll
            for (int q = 0; q < 4; q++) acc[i][j][q] = 0.0f;

    auto load_stage = [&](int slot, int kt) {
        uint32_t base = sb + slot * SLOT34;
        int k0 = kt * 64;
        #pragma unroll
        for (int i = 0; i < 4; i++) {
            int f = tid + i * 256;
            int row = f >> 3, ch = f & 7;
            uint32_t so = row * ROWB64 + ch * 16;
            cp16(base + A34_OFF + so, A + ((size_t)(m0 + row) << 10) + k0 + ch * 8);
            cp16(base + B34_OFF + so, B + ((size_t)(n0 + row) << 10) + k0 + ch * 8);
        }
        cp_commit();
    };

    load_stage(0, 0);

    const int arow = wm * 64 + (lane & 15);
    const int achk = lane >> 4;
    const int brow = wn * 32 + ((lane & 16) >> 1) + (lane & 7);
    const int bchk = (lane >> 3) & 1;

    for (int kt = 0; kt < KT34; kt++) {
        cp_wait0();
        __syncthreads();
        if (kt + 1 < KT34) load_stage((kt + 1) & 1, kt + 1);

        uint32_t sa = sb + (kt & 1) * SLOT34;
        #pragma unroll
        for (int ks = 0; ks < 4; ks++) {
            uint32_t a_h[4][4], b_h[2][4];
            #pragma unroll
            for (int mt = 0; mt < 4; mt++)
                ldsm4(a_h[mt], sa + A34_OFF + (arow + mt * 16) * ROWB64 + (ks * 2 + achk) * 16);
            #pragma unroll
            for (int p = 0; p < 2; p++)
                ldsm4(b_h[p], sa + B34_OFF + (brow + p * 16) * ROWB64 + (ks * 2 + bchk) * 16);
            #pragma unroll
            for (int mt = 0; mt < 4; mt++)
                #pragma unroll
                for (int nt = 0; nt < 4; nt++)
                    mma_fp16(acc[mt][nt], a_h[mt], &b_h[nt >> 1][(nt & 1) * 2]);
        }
    }

    #pragma unroll
    for (int mt = 0; mt < 4; mt++) {
        int mr = m0 + wm * 64 + mt * 16 + (lane >> 2);
        float s0 = scb[mr], s1 = scb[mr + 8];
        #pragma unroll
        for (int nt = 0; nt < 4; nt++) {
            int nc = n0 + wn * 32 + nt * 8 + (lane & 3) * 2;
            size_t i0 = ((size_t)mr << 10) + nc;
            size_t i1 = i0 + (8 << 10);
            *(float2*)(C + i0) = make_float2(acc[mt][nt][0] * s0, acc[mt][nt][1] * s0);
            *(float2*)(C + i1) = make_float2(acc[mt][nt][2] * s1, acc[mt][nt][3] * s1);
        }
    }
}

// ---------------- elementwise / reduction kernels ----------------
__global__ void split_kernel(const float* __restrict__ x, __half* __restrict__ h,
                             __half* __restrict__ l)
{
    size_t i = ((size_t)blockIdx.x * 256 + threadIdx.x) * 4;
    float4 v = *(const float4*)(x + i);
    union { __half hh[4]; uint2 u; } ph, pl;
    float f[4] = {v.x, v.y, v.z, v.w};
    #pragma unroll
    for (int j = 0; j < 4; j++) {
        __half b = __float2half_rn(f[j]);
        ph.hh[j] = b;
        pl.hh[j] = __float2half_rn(f[j] - __half2float(b));
    }
    *(uint2*)(h + i) = ph.u;
    *(uint2*)(l + i) = pl.u;
}

__global__ void wtrans_kernel(const float* __restrict__ W, __half* __restrict__ h,
                              __half* __restrict__ l)
{
    __shared__ float tile[32][33];
    int e0 = blockIdx.x << 5, d0 = blockIdx.y << 5;
    int tx = threadIdx.x, ty = threadIdx.y;
    #pragma unroll
    for (int j = 0; j < 4; j++) {
        int r = ty + (j << 3);
        tile[r][tx] = W[(size_t)(d0 + r) * NN + e0 + tx];
    }
    __syncthreads();
    #pragma unroll
    for (int j = 0; j < 4; j++) {
        int r = ty + (j << 3);
        float v = tile[tx][r];
        __half hh = __float2half_rn(v);
        size_t o = (size_t)(e0 + r) * NN + d0 + tx;
        h[o] = hh;
        l[o] = __float2half_rn(v - __half2float(hh));
    }
}

__global__ void pmax_kernel(const float* __restrict__ cc, float* __restrict__ pm)
{
    int b = blockIdx.z, sc = blockIdx.y;
    int t = blockIdx.x * 256 + threadIdx.x;
    const float* p = cc + ((size_t)b << 20) + ((size_t)sc << 17) + t;
    float m = -INFINITY;
    #pragma unroll 8
    for (int s = 0; s < 128; s++) m = fmaxf(m, p[(size_t)s << 10]);
    pm[((b << 3) + sc) * NN + t] = m;
}

__global__ void mcred_kernel(const float* __restrict__ pm, float* __restrict__ mc)
{
    int b = blockIdx.y;
    int t = blockIdx.x * 256 + threadIdx.x;
    float m = -INFINITY;
    #pragma unroll
    for (int c = 0; c < 8; c++) m = fmaxf(m, pm[((b << 3) + c) * NN + t]);
    mc[b * NN + t] = m;
}

// E_T[t][s] = exp(cc[s][t] - mc[t]) as fp16 (transposed write)
__global__ void expT_kernel(const float* __restrict__ cc, const float* __restrict__ mc,
                            __half* __restrict__ E)
{
    __shared__ float tile[32][33];
    int b = blockIdx.z;
    int s0 = blockIdx.x << 5, t0 = blockIdx.y << 5;
    int tx = threadIdx.x, ty = threadIdx.y;
    size_t cb = (size_t)b << 20;
    #pragma unroll
    for (int j = 0; j < 4; j++) {
        int r = ty + (j << 3);
        tile[r][tx] = cc[cb + ((size_t)(s0 + r) << 10) + t0 + tx];
    }
    __syncthreads();
    #pragma unroll
    for (int j = 0; j < 4; j++) {
        int r = ty + (j << 3);
        float m = mc[b * NN + t0 + r];
        float e = __expf(tile[tx][r] - m);
        E[cb + ((size_t)(t0 + r) << 10) + s0 + tx] = __float2half_rn(e);
    }
}

// invc[b][t] = 1 / sum_s E_T[b][t][s]  (sums the quantized weights -> consistent norm)
__global__ void sumET_kernel(const __half* __restrict__ E, float* __restrict__ invc)
{
    int b = blockIdx.y;
    int w = threadIdx.x >> 5, lane = threadIdx.x & 31;
    int t = blockIdx.x * 8 + w;
    const __half* row = E + ((size_t)b << 20) + ((size_t)t << 10);
    float s = 0.0f;
    #pragma unroll
    for (int i = 0; i < 4; i++) {
        uint4 q = *(const uint4*)(row + i * 256 + lane * 8);
        const __half2* h2 = (const __half2*)&q;
        #pragma unroll
        for (int j = 0; j < 4; j++) {
            float2 f = __half22float2(h2[j]);
            s += f.x + f.y;
        }
    }
    #pragma unroll
    for (int o = 16; o > 0; o >>= 1) s += __shfl_xor_sync(0xffffffff, s, o);
    if (lane == 0) invc[b * NN + t] = 1.0f / s;
}

// row softmax: E_r (fp16) + invr from quantized sums
__global__ void exprow_kernel(const float* __restrict__ cc, __half* __restrict__ E,
                              float* __restrict__ invr)
{
    __shared__ float red[256];
    int b = blockIdx.y, s = blockIdx.x;
    size_t base = ((size_t)b << 20) + ((size_t)s << 10);
    int t0 = threadIdx.x * 4;
    float4 q = *(const float4*)(cc + base + t0);
    float m = fmaxf(fmaxf(q.x, q.y), fmaxf(q.z, q.w));
    red[threadIdx.x] = m;
    __syncthreads();
    #pragma unroll
    for (int o = 128; o > 0; o >>= 1) {
        if (threadIdx.x < o) red[threadIdx.x] = fmaxf(red[threadIdx.x], red[threadIdx.x + o]);
        __syncthreads();
    }
    m = red[0];
    __syncthreads();
    float e[4] = {__expf(q.x - m), __expf(q.y - m), __expf(q.z - m), __expf(q.w - m)};
    union { __half h[4]; uint2 u; } ph;
    float qs = 0.0f;
    #pragma unroll
    for (int j = 0; j < 4; j++) {
        ph.h[j] = __float2half_rn(e[j]);
        qs += __half2float(ph.h[j]);          // quantized sum -> consistent normalization
    }
    *(uint2*)(E + base + t0) = ph.u;
    red[threadIdx.x] = qs;
    __syncthreads();
    #pragma unroll
    for (int o = 128; o > 0; o >>= 1) {
        if (threadIdx.x < o) red[threadIdx.x] += red[threadIdx.x + o];
        __syncthreads();
    }
    if (threadIdx.x == 0) invr[b * NN + s] = 1.0f / red[0];
}

// ---------------- host ----------------
extern "C" void kernel_launch(void* const* d_in, const int* in_sizes, int n_in,
                              void* d_out, int out_size)
{
    const float* f1 = (const float*)d_in[0];
    const float* f2 = (const float*)d_in[1];
    const float* W  = (const float*)d_in[2];
    float* out1 = (float*)d_out;
    float* out2 = out1 + ((size_t)NB << 20);

    __half *f1h, *f1l, *f2h, *f2l, *wth, *wtl, *a1h, *a1l, *et, *er;
    float *cc, *pm, *mc, *invc, *invr;
    cudaGetSymbolAddress((void**)&f1h, g_f1h); cudaGetSymbolAddress((void**)&f1l, g_f1l);
    cudaGetSymbolAddress((void**)&f2h, g_f2h); cudaGetSymbolAddress((void**)&f2l, g_f2l);
    cudaGetSymbolAddress((void**)&wth, g_wth); cudaGetSymbolAddress((void**)&wtl, g_wtl);
    cudaGetSymbolAddress((void**)&a1h, g_a1h); cudaGetSymbolAddress((void**)&a1l, g_a1l);
    cudaGetSymbolAddress((void**)&et, g_et);   cudaGetSymbolAddress((void**)&er, g_er);
    cudaGetSymbolAddress((void**)&cc, g_cc);   cudaGetSymbolAddress((void**)&pm, g_pmax);
    cudaGetSymbolAddress((void**)&mc, g_mc);   cudaGetSymbolAddress((void**)&invc, g_invc);
    cudaGetSymbolAddress((void**)&invr, g_invr);

    cudaFuncSetAttribute(gemm_kernel<true>,  cudaFuncAttributeMaxDynamicSharedMemorySize, SMEM_DYN);
    cudaFuncSetAttribute(gemm_kernel<false>, cudaFuncAttributeMaxDynamicSharedMemorySize, SMEM_DYN);
    cudaFuncSetAttribute(gemm34_kernel, cudaFuncAttributeMaxDynamicSharedMemorySize, SMEM34);

    const size_t MBe = (size_t)1 << 20;
    dim3 gg(8, 8, NB);       // logit GEMMs: 1024 CTAs
    dim3 gg34(8, 8, 2 * NB); // fused attention GEMMs: 2048 CTAs

    // fp16 splits
    split_kernel<<<16384, 256>>>(f1, f1h, f1l);
    split_kernel<<<16384, 256>>>(f2, f2h, f2l);
    wtrans_kernel<<<dim3(32, 32), dim3(32, 8)>>>(W, wth, wtl);

    // 1. a1 = f1 @ W (3-product) -> fp16 split
    gemm_kernel<true><<<gg, 256, SMEM_DYN>>>(f1h, f1l, wth, wtl,
                                             nullptr, a1h, a1l, MBe, 0, MBe);
    // 2. cc = a1 @ f2^T (3-product) -> fp32
    gemm_kernel<false><<<gg, 256, SMEM_DYN>>>(a1h, a1l, f2h, f2l,
                                              cc, nullptr, nullptr, MBe, MBe, MBe);
    // 3. column maxes (partial + reduce)
    pmax_kernel<<<dim3(4, 8, NB), 256>>>(cc, pm);
    mcred_kernel<<<dim3(4, NB), 256>>>(pm, mc);
    // 4. E_T (fp16, transposed)
    expT_kernel<<<dim3(32, 32, NB), dim3(32, 8)>>>(cc, mc, et);
    // 5. invc from quantized E_T row sums
    sumET_kernel<<<dim3(128, NB), 256>>>(et, invc);
    // 6. row softmax (fp16 E_r + invr, quantized sums)
    exprow_kernel<<<dim3(NN, NB), 256>>>(cc, er, invr);
    // 7. fused attention GEMMs, single product, BK=64
    gemm34_kernel<<<gg34, 256, SMEM34>>>(et, f1h, invc, out1,
                                         er, f2h, invr, out2);
}

// round 13
// speedup vs baseline: 1.6053x; 1.0157x over previous
#include <cuda_runtime.h>
#include <cuda_fp16.h>
#include <math.h>
#include <stdint.h>

#define NB 16
#define NN 1024

// ---------------- helpers ----------------
__device__ __forceinline__ uint32_t smem_to_u32(const void* p) {
    uint32_t a;
    asm("{ .reg .u64 t; cvta.to.shared.u64 t, %1; cvt.u32.u64 %0, t; }" : "=r"(a) : "l"(p));
    return a;
}
__device__ __forceinline__ void cp16(uint32_t dst, const void* src) {
    asm volatile("cp.async.cg.shared.global [%0], [%1], 16;" :: "r"(dst), "l"(src));
}
__device__ __forceinline__ void cp_commit() { asm volatile("cp.async.commit_group;" ::: "memory"); }
__device__ __forceinline__ void cp_wait0()  { asm volatile("cp.async.wait_group 0;" ::: "memory"); }

__device__ __forceinline__ void ldsm4(uint32_t* r, uint32_t addr) {
    asm volatile("ldmatrix.sync.aligned.m8n8.x4.shared.b16 {%0,%1,%2,%3}, [%4];"
                 : "=r"(r[0]), "=r"(r[1]), "=r"(r[2]), "=r"(r[3]) : "r"(addr));
}
__device__ __forceinline__ void mma_fp16(float* c, const uint32_t* a, const uint32_t* b) {
    asm volatile(
        "mma.sync.aligned.m16n8k16.row.col.f32.f16.f16.f32 "
        "{%0,%1,%2,%3}, {%4,%5,%6,%7}, {%8,%9}, {%0,%1,%2,%3};"
        : "+f"(c[0]), "+f"(c[1]), "+f"(c[2]), "+f"(c[3])
        : "r"(a[0]), "r"(a[1]), "r"(a[2]), "r"(a[3]), "r"(b[0]), "r"(b[1]));
}

// ---------------- scratch (device globals) ----------------
#define TOT ((size_t)NB * NN * NN)
__device__ __half g_f1h[TOT], g_f1l[TOT];
__device__ __half g_f2h[TOT], g_f2l[TOT];
__device__ __half g_wth[NN * NN], g_wtl[NN * NN];
__device__ __half g_a1h[TOT], g_a1l[TOT];
__device__ __half g_et[TOT];               // E_T (single fp16)
__device__ __half g_er[TOT];               // E_r (single fp16)
__device__ float g_cc[TOT];
__device__ float g_pmax[NB * 8 * NN];      // partial col maxes (from GEMM2 epilogue)
__device__ float g_pmaxr[NB * 8 * NN];     // partial row maxes (from GEMM2 epilogue)
__device__ float g_mc[NB * NN], g_mr[NB * NN], g_invc[NB * NN], g_invr[NB * NN];

// ---------------- fp16 logit GEMM (proven layout) ----------------
// C[M,N] = A[M,K] · B[N,K]^T, 3 products (hh,hl,lh).
// 256 threads, 8 warps (2m x 4n), 128x128 tile, warp tile 64x32, BK=32,
// 2-stage cp.async, 2 CTAs/SM. STATS: emit partial row/col maxes of C.
#define BK 32
#define ROWB 80
#define AH_OFF 0
#define AL_OFF (128 * ROWB)
#define BH_OFF (2 * 128 * ROWB)
#define BL_OFF (3 * 128 * ROWB)
#define SLOTB (4 * 128 * ROWB)          // 40960
#define SMEM_DYN (2 * SLOTB)            // 81920 -> 2 CTAs/SM
#define KT 32

template<bool SPLIT_OUT, bool STATS>
__global__ __launch_bounds__(256, 2)
void gemm_kernel(const __half* __restrict__ Ahg, const __half* __restrict__ Alg,
                 const __half* __restrict__ Bhg, const __half* __restrict__ Blg,
                 float* __restrict__ Cg, __half* __restrict__ Chg, __half* __restrict__ Clg,
                 float* __restrict__ pmg, float* __restrict__ pmrg,
                 size_t sA, size_t sB, size_t sC)
{
    extern __shared__ char dsm[];
    const uint32_t sb = smem_to_u32(dsm);
    const size_t bz = blockIdx.z;
    const __half* Ah = Ahg + bz * sA;
    const __half* Al = Alg + bz * sA;
    const __half* Bh = Bhg + bz * sB;
    const __half* Bl = Blg + bz * sB;

    const int tid = threadIdx.x;
    const int lane = tid & 31;
    const int w = tid >> 5;
    const int wm = w & 1;
    const int wn = w >> 1;
    const int m0 = blockIdx.y * 128;
    const int n0 = blockIdx.x * 128;

    float acc[4][4][4];
    #pragma unroll
    for (int i = 0; i < 4; i++)
        #pragma unroll
        for (int j = 0; j < 4; j++)
            #pragma unroll
            for (int q = 0; q < 4; q++) acc[i][j][q] = 0.0f;

    auto load_stage = [&](int slot, int kt) {
        uint32_t base = sb + slot * SLOTB;
        int k0 = kt * BK;
        #pragma unroll
        for (int i = 0; i < 2; i++) {
            int f = tid + i * 256;
            int row = f >> 2, ch = f & 3;
            uint32_t so = row * ROWB + ch * 16;
            size_t gA = ((size_t)(m0 + row) << 10) + k0 + ch * 8;
            size_t gB = ((size_t)(n0 + row) << 10) + k0 + ch * 8;
            cp16(base + AH_OFF + so, Ah + gA);
            cp16(base + AL_OFF + so, Al + gA);
            cp16(base + BH_OFF + so, Bh + gB);
            cp16(base + BL_OFF + so, Bl + gB);
        }
        cp_commit();
    };

    load_stage(0, 0);

    const int arow = wm * 64 + (lane & 15);
    const int achk = lane >> 4;
    const int brow = wn * 32 + ((lane & 16) >> 1) + (lane & 7);
    const int bchk = (lane >> 3) & 1;

    for (int kt = 0; kt < KT; kt++) {
        cp_wait0();
        __syncthreads();
        if (kt + 1 < KT) load_stage((kt + 1) & 1, kt + 1);

        uint32_t sa = sb + (kt & 1) * SLOTB;
        #pragma unroll
        for (int ks = 0; ks < 2; ks++) {
            uint32_t a_h[4][4], a_l[4][4], b_h[2][4], b_l[2][4];
            #pragma unroll
            for (int mt = 0; mt < 4; mt++) {
                uint32_t ad = sa + AH_OFF + (arow + mt * 16) * ROWB + (ks * 2 + achk) * 16;
                ldsm4(a_h[mt], ad);
                ldsm4(a_l[mt], ad + (AL_OFF - AH_OFF));
            }
            #pragma unroll
            for (int p = 0; p < 2; p++) {
                uint32_t bd = sa + BH_OFF + (brow + p * 16) * ROWB + (ks * 2 + bchk) * 16;
                ldsm4(b_h[p], bd);
                ldsm4(b_l[p], bd + (BL_OFF - BH_OFF));
            }
            #pragma unroll
            for (int mt = 0; mt < 4; mt++)
                #pragma unroll
                for (int nt = 0; nt < 4; nt++)
                    mma_fp16(acc[mt][nt], a_h[mt], &b_h[nt >> 1][(nt & 1) * 2]);
            #pragma unroll
            for (int mt = 0; mt < 4; mt++)
                #pragma unroll
                for (int nt = 0; nt < 4; nt++)
                    mma_fp16(acc[mt][nt], a_h[mt], &b_l[nt >> 1][(nt & 1) * 2]);
            #pragma unroll
            for (int mt = 0; mt < 4; mt++)
                #pragma unroll
                for (int nt = 0; nt < 4; nt++)
                    mma_fp16(acc[mt][nt], a_l[mt], &b_h[nt >> 1][(nt & 1) * 2]);
        }
    }

    // ---- epilogue: C writes ----
    #pragma unroll
    for (int mt = 0; mt < 4; mt++) {
        int mr = m0 + wm * 64 + mt * 16 + (lane >> 2);
        #pragma unroll
        for (int nt = 0; nt < 4; nt++) {
            int nc = n0 + wn * 32 + nt * 8 + (lane & 3) * 2;
            size_t i0 = bz * sC + ((size_t)mr << 10) + nc;
            size_t i1 = i0 + (8 << 10);
            float v00 = acc[mt][nt][0], v01 = acc[mt][nt][1];
            float v10 = acc[mt][nt][2], v11 = acc[mt][nt][3];
            if (SPLIT_OUT) {
                __half h00 = __float2half_rn(v00), h01 = __float2half_rn(v01);
                __half h10 = __float2half_rn(v10), h11 = __float2half_rn(v11);
                *(__half2*)(Chg + i0) = __halves2half2(h00, h01);
                *(__half2*)(Chg + i1) = __halves2half2(h10, h11);
                *(__half2*)(Clg + i0) = __halves2half2(
                    __float2half_rn(v00 - __half2float(h00)),
                    __float2half_rn(v01 - __half2float(h01)));
                *(__half2*)(Clg + i1) = __halves2half2(
                    __float2half_rn(v10 - __half2float(h10)),
                    __float2half_rn(v11 - __half2float(h11)));
            } else {
                *(float2*)(Cg + i0) = make_float2(v00, v01);
                *(float2*)(Cg + i1) = make_float2(v10, v11);
            }
        }
    }

    // ---- epilogue stats: partial col/row maxes of the tile (STATS only) ----
    if (STATS) {
        __syncthreads();                        // pipeline smem now reusable
        float* scm = (float*)dsm;               // [128] col maxes
        float* srm = (float*)(dsm + 512);       // [4][128] row maxes per wn

        // per-thread col maxes over its 8 m-values, per (nt, col-parity)
        float cmax[4][2];
        #pragma unroll
        for (int nt = 0; nt < 4; nt++)
            #pragma unroll
            for (int par = 0; par < 2; par++) {
                float m = fmaxf(acc[0][nt][par], acc[0][nt][par + 2]);
                #pragma unroll
                for (int mt = 1; mt < 4; mt++)
                    m = fmaxf(m, fmaxf(acc[mt][nt][par], acc[mt][nt][par + 2]));
                cmax[nt][par] = m;
            }
        // reduce across lanes sharing a column (lane>>2 varies): xor 4,8,16
        #pragma unroll
        for (int o = 4; o <= 16; o <<= 1)
            #pragma unroll
            for (int nt = 0; nt < 4; nt++)
                #pragma unroll
                for (int par = 0; par < 2; par++)
                    cmax[nt][par] = fmaxf(cmax[nt][par],
                                          __shfl_xor_sync(0xffffffff, cmax[nt][par], o));
        if (wm == 0 && lane < 4) {
            #pragma unroll
            for (int nt = 0; nt < 4; nt++)
                #pragma unroll
                for (int par = 0; par < 2; par++)
                    scm[wn * 32 + nt * 8 + lane * 2 + par] = cmax[nt][par];
        }
        __syncthreads();
        if (wm == 1 && lane < 4) {
            #pragma unroll
            for (int nt = 0; nt < 4; nt++)
                #pragma unroll
                for (int par = 0; par < 2; par++) {
                    int c = wn * 32 + nt * 8 + lane * 2 + par;
                    scm[c] = fmaxf(scm[c], cmax[nt][par]);
                }
        }

        // per-thread row maxes over its 8 n-values, per (mt, row-half)
        float rmax[4][2];
        #pragma unroll
        for (int mt = 0; mt < 4; mt++)
            #pragma unroll
            for (int qr = 0; qr < 2; qr++) {
                float m = fmaxf(acc[mt][0][qr * 2], acc[mt][0][qr * 2 + 1]);
                #pragma unroll
                for (int nt = 1; nt < 4; nt++)
                    m = fmaxf(m, fmaxf(acc[mt][nt][qr * 2], acc[mt][nt][qr * 2 + 1]));
                rmax[mt][qr] = m;
            }
        // reduce across lanes sharing a row (lane&3 varies): xor 1,2
        #pragma unroll
        for (int o = 1; o <= 2; o <<= 1)
            #pragma unroll
            for (int mt = 0; mt < 4; mt++)
                #pragma unroll
                for (int qr = 0; qr < 2; qr++)
                    rmax[mt][qr] = fmaxf(rmax[mt][qr],
                                         __shfl_xor_sync(0xffffffff, rmax[mt][qr], o));
        if ((lane & 3) == 0) {
            #pragma unroll
            for (int mt = 0; mt < 4; mt++)
                #pragma unroll
                for (int qr = 0; qr < 2; qr++)
                    srm[wn * 128 + wm * 64 + mt * 16 + (lane >> 2) + qr * 8] = rmax[mt][qr];
        }
        __syncthreads();

        if (tid < 128) {
            pmg[((bz << 3) + blockIdx.y) * NN + n0 + tid] = scm[tid];
            float m = fmaxf(fmaxf(srm[tid], srm[128 + tid]),
                            fmaxf(srm[256 + tid], srm[384 + tid]));
            pmrg[((bz << 3) + blockIdx.x) * NN + m0 + tid] = m;
        }
    }
}

// ---------------- single-product attention GEMM, BK=64 ----------------
#define ROWB64 144
#define A34_OFF 0
#define B34_OFF (128 * ROWB64)
#define SLOT34 (2 * 128 * ROWB64)        // 36864
#define SMEM34 (2 * SLOT34)              // 73728
#define KT34 16

__global__ __launch_bounds__(256, 2)
void gemm34_kernel(const __half* __restrict__ A3, const __half* __restrict__ B3,
                   const float* __restrict__ sc3, float* __restrict__ C3,
                   const __half* __restrict__ A4, const __half* __restrict__ B4,
                   const float* __restrict__ sc4, float* __restrict__ C4)
{
    extern __shared__ char dsm[];
    const uint32_t sb = smem_to_u32(dsm);
    const int z = blockIdx.z;
    const size_t off = (size_t)(z & 15) << 20;
    const int bn = (z & 15) * NN;
    const __half* A = (z < 16) ? A3 + off : A4 + off;
    const __half* B = (z < 16) ? B3 + off : B4 + off;
    const float* scb = ((z < 16) ? sc3 : sc4) + bn;
    float* C = ((z < 16) ? C3 : C4) + off;

    const int tid = threadIdx.x;
    const int lane = tid & 31;
    const int w = tid >> 5;
    const int wm = w & 1;
    const int wn = w >> 1;
    const int m0 = blockIdx.y * 128;
    const int n0 = blockIdx.x * 128;

    float acc[4][4][4];
    #pragma unroll
    for (int i = 0; i < 4; i++)
        #pragma unroll
        for (int j = 0; j < 4; j++)
            #pragma unroll
            for (int q = 0; q < 4; q++) acc[i][j][q] = 0.0f;

    auto load_stage = [&](int slot, int kt) {
        uint32_t base = sb + slot * SLOT34;
        int k0 = kt * 64;
        #pragma unroll
        for (int i = 0; i < 4; i++) {
            int f = tid + i * 256;
            int row = f >> 3, ch = f & 7;
            uint32_t so = row * ROWB64 + ch * 16;
            cp16(base + A34_OFF + so, A + ((size_t)(m0 + row) << 10) + k0 + ch * 8);
            cp16(base + B34_OFF + so, B + ((size_t)(n0 + row) << 10) + k0 + ch * 8);
        }
        cp_commit();
    };

    load_stage(0, 0);

    const int arow = wm * 64 + (lane & 15);
    const int achk = lane >> 4;
    const int brow = wn * 32 + ((lane & 16) >> 1) + (lane & 7);
    const int bchk = (lane >> 3) & 1;

    for (int kt = 0; kt < KT34; kt++) {
        cp_wait0();
        __syncthreads();
        if (kt + 1 < KT34) load_stage((kt + 1) & 1, kt + 1);

        uint32_t sa = sb + (kt & 1) * SLOT34;
        #pragma unroll
        for (int ks = 0; ks < 4; ks++) {
            uint32_t a_h[4][4], b_h[2][4];
            #pragma unroll
            for (int mt = 0; mt < 4; mt++)
                ldsm4(a_h[mt], sa + A34_OFF + (arow + mt * 16) * ROWB64 + (ks * 2 + achk) * 16);
            #pragma unroll
            for (int p = 0; p < 2; p++)
                ldsm4(b_h[p], sa + B34_OFF + (brow + p * 16) * ROWB64 + (ks * 2 + bchk) * 16);
            #pragma unroll
            for (int mt = 0; mt < 4; mt++)
                #pragma unroll
                for (int nt = 0; nt < 4; nt++)
                    mma_fp16(acc[mt][nt], a_h[mt], &b_h[nt >> 1][(nt & 1) * 2]);
        }
    }

    #pragma unroll
    for (int mt = 0; mt < 4; mt++) {
        int mr = m0 + wm * 64 + mt * 16 + (lane >> 2);
        float s0 = scb[mr], s1 = scb[mr + 8];
        #pragma unroll
        for (int nt = 0; nt < 4; nt++) {
            int nc = n0 + wn * 32 + nt * 8 + (lane & 3) * 2;
            size_t i0 = ((size_t)mr << 10) + nc;
            size_t i1 = i0 + (8 << 10);
            *(float2*)(C + i0) = make_float2(acc[mt][nt][0] * s0, acc[mt][nt][1] * s0);
            *(float2*)(C + i1) = make_float2(acc[mt][nt][2] * s1, acc[mt][nt][3] * s1);
        }
    }
}

// ---------------- elementwise / reduction kernels ----------------
// merged split for f1 and f2
__global__ void split2_kernel(const float* __restrict__ x1, __half* __restrict__ h1,
                              __half* __restrict__ l1,
                              const float* __restrict__ x2, __half* __restrict__ h2,
                              __half* __restrict__ l2)
{
    int bid = blockIdx.x;
    const float* x;
    __half *h, *l;
    if (bid < 16384) { x = x1; h = h1; l = l1; }
    else { x = x2; h = h2; l = l2; bid -= 16384; }
    size_t i = ((size_t)bid * 256 + threadIdx.x) * 4;
    float4 v = *(const float4*)(x + i);
    union { __half hh[4]; uint2 u; } ph, pl;
    float f[4] = {v.x, v.y, v.z, v.w};
    #pragma unroll
    for (int j = 0; j < 4; j++) {
        __half b = __float2half_rn(f[j]);
        ph.hh[j] = b;
        pl.hh[j] = __float2half_rn(f[j] - __half2float(b));
    }
    *(uint2*)(h + i) = ph.u;
    *(uint2*)(l + i) = pl.u;
}

__global__ void wtrans_kernel(const float* __restrict__ W, __half* __restrict__ h,
                              __half* __restrict__ l)
{
    __shared__ float tile[32][33];
    int e0 = blockIdx.x << 5, d0 = blockIdx.y << 5;
    int tx = threadIdx.x, ty = threadIdx.y;
    #pragma unroll
    for (int j = 0; j < 4; j++) {
        int r = ty + (j << 3);
        tile[r][tx] = W[(size_t)(d0 + r) * NN + e0 + tx];
    }
    __syncthreads();
    #pragma unroll
    for (int j = 0; j < 4; j++) {
        int r = ty + (j << 3);
        float v = tile[tx][r];
        __half hh = __float2half_rn(v);
        size_t o = (size_t)(e0 + r) * NN + d0 + tx;
        h[o] = hh;
        l[o] = __float2half_rn(v - __half2float(hh));
    }
}

// reduce 8 partials -> max (used for both mc and mr)
__global__ void maxred_kernel(const float* __restrict__ pm, float* __restrict__ mc)
{
    int b = blockIdx.y;
    int t = blockIdx.x * 256 + threadIdx.x;
    float m = -INFINITY;
    #pragma unroll
    for (int c = 0; c < 8; c++) m = fmaxf(m, pm[((b << 3) + c) * NN + t]);
    mc[b * NN + t] = m;
}

// E_T[t][s] = exp(cc[s][t] - mc[t]) as fp16 (transposed write)
__global__ void expT_kernel(const float* __restrict__ cc, const float* __restrict__ mc,
                            __half* __restrict__ E)
{
    __shared__ float tile[32][33];
    int b = blockIdx.z;
    int s0 = blockIdx.x << 5, t0 = blockIdx.y << 5;
    int tx = threadIdx.x, ty = threadIdx.y;
    size_t cb = (size_t)b << 20;
    #pragma unroll
    for (int j = 0; j < 4; j++) {
        int r = ty + (j << 3);
        tile[r][tx] = cc[cb + ((size_t)(s0 + r) << 10) + t0 + tx];
    }
    __syncthreads();
    #pragma unroll
    for (int j = 0; j < 4; j++) {
        int r = ty + (j << 3);
        float m = mc[b * NN + t0 + r];
        float e = __expf(tile[tx][r] - m);
        E[cb + ((size_t)(t0 + r) << 10) + s0 + tx] = __float2half_rn(e);
    }
}

// invc[b][t] = 1 / sum_s E_T[b][t][s]  (quantized weights -> consistent norm)
__global__ void sumET_kernel(const __half* __restrict__ E, float* __restrict__ invc)
{
    int b = blockIdx.y;
    int w = threadIdx.x >> 5, lane = threadIdx.x & 31;
    int t = blockIdx.x * 8 + w;
    const __half* row = E + ((size_t)b << 20) + ((size_t)t << 10);
    float s = 0.0f;
    #pragma unroll
    for (int i = 0; i < 4; i++) {
        uint4 q = *(const uint4*)(row + i * 256 + lane * 8);
        const __half2* h2 = (const __half2*)&q;
        #pragma unroll
        for (int j = 0; j < 4; j++) {
            float2 f = __half22float2(h2[j]);
            s += f.x + f.y;
        }
    }
    #pragma unroll
    for (int o = 16; o > 0; o >>= 1) s += __shfl_xor_sync(0xffffffff, s, o);
    if (lane == 0) invc[b * NN + t] = 1.0f / s;
}

// row softmax: E_r (fp16) + invr from quantized sums; row max precomputed (mr)
__global__ void exprow_kernel(const float* __restrict__ cc, const float* __restrict__ mr,
                              __half* __restrict__ E, float* __restrict__ invr)
{
    __shared__ float red[256];
    int b = blockIdx.y, s = blockIdx.x;
    size_t base = ((size_t)b << 20) + ((size_t)s << 10);
    int t0 = threadIdx.x * 4;
    float4 q = *(const float4*)(cc + base + t0);
    float m = mr[b * NN + s];
    float e[4] = {__expf(q.x - m), __expf(q.y - m), __expf(q.z - m), __expf(q.w - m)};
    union { __half h[4]; uint2 u; } ph;
    float qs = 0.0f;
    #pragma unroll
    for (int j = 0; j < 4; j++) {
        ph.h[j] = __float2half_rn(e[j]);
        qs += __half2float(ph.h[j]);
    }
    *(uint2*)(E + base + t0) = ph.u;
    red[threadIdx.x] = qs;
    __syncthreads();
    #pragma unroll
    for (int o = 128; o > 0; o >>= 1) {
        if (threadIdx.x < o) red[threadIdx.x] += red[threadIdx.x + o];
        __syncthreads();
    }
    if (threadIdx.x == 0) invr[b * NN + s] = 1.0f / red[0];
}

// ---------------- host ----------------
extern "C" void kernel_launch(void* const* d_in, const int* in_sizes, int n_in,
                              void* d_out, int out_size)
{
    const float* f1 = (const float*)d_in[0];
    const float* f2 = (const float*)d_in[1];
    const float* W  = (const float*)d_in[2];
    float* out1 = (float*)d_out;
    float* out2 = out1 + ((size_t)NB << 20);

    __half *f1h, *f1l, *f2h, *f2l, *wth, *wtl, *a1h, *a1l, *et, *er;
    float *cc, *pm, *pmr, *mc, *mr, *invc, *invr;
    cudaGetSymbolAddress((void**)&f1h, g_f1h); cudaGetSymbolAddress((void**)&f1l, g_f1l);
    cudaGetSymbolAddress((void**)&f2h, g_f2h); cudaGetSymbolAddress((void**)&f2l, g_f2l);
    cudaGetSymbolAddress((void**)&wth, g_wth); cudaGetSymbolAddress((void**)&wtl, g_wtl);
    cudaGetSymbolAddress((void**)&a1h, g_a1h); cudaGetSymbolAddress((void**)&a1l, g_a1l);
    cudaGetSymbolAddress((void**)&et, g_et);   cudaGetSymbolAddress((void**)&er, g_er);
    cudaGetSymbolAddress((void**)&cc, g_cc);
    cudaGetSymbolAddress((void**)&pm, g_pmax); cudaGetSymbolAddress((void**)&pmr, g_pmaxr);
    cudaGetSymbolAddress((void**)&mc, g_mc);   cudaGetSymbolAddress((void**)&mr, g_mr);
    cudaGetSymbolAddress((void**)&invc, g_invc);
    cudaGetSymbolAddress((void**)&invr, g_invr);

    cudaFuncSetAttribute(gemm_kernel<true,  false>, cudaFuncAttributeMaxDynamicSharedMemorySize, SMEM_DYN);
    cudaFuncSetAttribute(gemm_kernel<false, true>,  cudaFuncAttributeMaxDynamicSharedMemorySize, SMEM_DYN);
    cudaFuncSetAttribute(gemm34_kernel, cudaFuncAttributeMaxDynamicSharedMemorySize, SMEM34);

    const size_t MBe = (size_t)1 << 20;
    dim3 gg(8, 8, NB);       // logit GEMMs: 1024 CTAs
    dim3 gg34(8, 8, 2 * NB); // fused attention GEMMs: 2048 CTAs

    // fp16 splits (merged f1+f2) + W transpose split
    split2_kernel<<<32768, 256>>>(f1, f1h, f1l, f2, f2h, f2l);
    wtrans_kernel<<<dim3(32, 32), dim3(32, 8)>>>(W, wth, wtl);

    // 1. a1 = f1 @ W (3-product) -> fp16 split
    gemm_kernel<true,  false><<<gg, 256, SMEM_DYN>>>(f1h, f1l, wth, wtl,
                                                     nullptr, a1h, a1l,
                                                     nullptr, nullptr, MBe, 0, MBe);
    // 2. cc = a1 @ f2^T (3-product) -> fp32, with fused partial row/col maxes
    gemm_kernel<false, true><<<gg, 256, SMEM_DYN>>>(a1h, a1l, f2h, f2l,
                                                    cc, nullptr, nullptr,
                                                    pm, pmr, MBe, MBe, MBe);
    // 3. reduce partials -> mc (col maxes), mr (row maxes)
    maxred_kernel<<<dim3(4, NB), 256>>>(pm, mc);
    maxred_kernel<<<dim3(4, NB), 256>>>(pmr, mr);
    // 4. E_T (fp16, transposed)
    expT_kernel<<<dim3(32, 32, NB), dim3(32, 8)>>>(cc, mc, et);
    // 5. invc from quantized E_T row sums
    sumET_kernel<<<dim3(128, NB), 256>>>(et, invc);
    // 6. row softmax with precomputed mr
    exprow_kernel<<<dim3(NN, NB), 256>>>(cc, mr, er, invr);
    // 7. fused attention GEMMs, single product, BK=64
    gemm34_kernel<<<gg34, 256, SMEM34>>>(et, f1h, invc, out1,
                                         er, f2h, invr, out2);
}

// round 14
// speedup vs baseline: 1.6114x; 1.0038x over previous
#include <cuda_runtime.h>
#include <cuda_fp16.h>
#include <math.h>
#include <stdint.h>

#define NB 16
#define NN 1024

// ---------------- helpers ----------------
__device__ __forceinline__ uint32_t smem_to_u32(const void* p) {
    uint32_t a;
    asm("{ .reg .u64 t; cvta.to.shared.u64 t, %1; cvt.u32.u64 %0, t; }" : "=r"(a) : "l"(p));
    return a;
}
__device__ __forceinline__ void cp16(uint32_t dst, const void* src) {
    asm volatile("cp.async.cg.shared.global [%0], [%1], 16;" :: "r"(dst), "l"(src));
}
__device__ __forceinline__ void cp_commit() { asm volatile("cp.async.commit_group;" ::: "memory"); }
__device__ __forceinline__ void cp_wait0()  { asm volatile("cp.async.wait_group 0;" ::: "memory"); }

__device__ __forceinline__ void ldsm4(uint32_t* r, uint32_t addr) {
    asm volatile("ldmatrix.sync.aligned.m8n8.x4.shared.b16 {%0,%1,%2,%3}, [%4];"
                 : "=r"(r[0]), "=r"(r[1]), "=r"(r[2]), "=r"(r[3]) : "r"(addr));
}
__device__ __forceinline__ void mma_fp16(float* c, const uint32_t* a, const uint32_t* b) {
    asm volatile(
        "mma.sync.aligned.m16n8k16.row.col.f32.f16.f16.f32 "
        "{%0,%1,%2,%3}, {%4,%5,%6,%7}, {%8,%9}, {%0,%1,%2,%3};"
        : "+f"(c[0]), "+f"(c[1]), "+f"(c[2]), "+f"(c[3])
        : "r"(a[0]), "r"(a[1]), "r"(a[2]), "r"(a[3]), "r"(b[0]), "r"(b[1]));
}

// ---------------- scratch (device globals) ----------------
#define TOT ((size_t)NB * NN * NN)
__device__ __half g_f1h[TOT], g_f1l[TOT];
__device__ __half g_f2h[TOT], g_f2l[TOT];
__device__ __half g_wth[NN * NN], g_wtl[NN * NN];
__device__ __half g_a1h[TOT], g_a1l[TOT];
__device__ __half g_et[TOT];               // E_T (single fp16)
__device__ __half g_er[TOT];               // E_r (single fp16)
__device__ float g_cc[TOT];
__device__ float g_pmax[NB * 8 * NN];      // partial col maxes (GEMM2 epilogue)
__device__ float g_pmaxr[NB * 8 * NN];     // partial row maxes (GEMM2 epilogue)
__device__ float g_psc[32 * NB * NN];      // partial col-softmax sums (expboth)
__device__ float g_psr[32 * NB * NN];      // partial row-softmax sums (expboth)
__device__ float g_mc[NB * NN], g_mr[NB * NN], g_invc[NB * NN], g_invr[NB * NN];

// ---------------- fp16 logit GEMM (proven layout) ----------------
#define BK 32
#define ROWB 80
#define AH_OFF 0
#define AL_OFF (128 * ROWB)
#define BH_OFF (2 * 128 * ROWB)
#define BL_OFF (3 * 128 * ROWB)
#define SLOTB (4 * 128 * ROWB)          // 40960
#define SMEM_DYN (2 * SLOTB)            // 81920 -> 2 CTAs/SM
#define KT 32

template<bool SPLIT_OUT, bool STATS>
__global__ __launch_bounds__(256, 2)
void gemm_kernel(const __half* __restrict__ Ahg, const __half* __restrict__ Alg,
                 const __half* __restrict__ Bhg, const __half* __restrict__ Blg,
                 float* __restrict__ Cg, __half* __restrict__ Chg, __half* __restrict__ Clg,
                 float* __restrict__ pmg, float* __restrict__ pmrg,
                 size_t sA, size_t sB, size_t sC)
{
    extern __shared__ char dsm[];
    const uint32_t sb = smem_to_u32(dsm);
    const size_t bz = blockIdx.z;
    const __half* Ah = Ahg + bz * sA;
    const __half* Al = Alg + bz * sA;
    const __half* Bh = Bhg + bz * sB;
    const __half* Bl = Blg + bz * sB;

    const int tid = threadIdx.x;
    const int lane = tid & 31;
    const int w = tid >> 5;
    const int wm = w & 1;
    const int wn = w >> 1;
    const int m0 = blockIdx.y * 128;
    const int n0 = blockIdx.x * 128;

    float acc[4][4][4];
    #pragma unroll
    for (int i = 0; i < 4; i++)
        #pragma unroll
        for (int j = 0; j < 4; j++)
            #pragma unroll
            for (int q = 0; q < 4; q++) acc[i][j][q] = 0.0f;

    auto load_stage = [&](int slot, int kt) {
        uint32_t base = sb + slot * SLOTB;
        int k0 = kt * BK;
        #pragma unroll
        for (int i = 0; i < 2; i++) {
            int f = tid + i * 256;
            int row = f >> 2, ch = f & 3;
            uint32_t so = row * ROWB + ch * 16;
            size_t gA = ((size_t)(m0 + row) << 10) + k0 + ch * 8;
            size_t gB = ((size_t)(n0 + row) << 10) + k0 + ch * 8;
            cp16(base + AH_OFF + so, Ah + gA);
            cp16(base + AL_OFF + so, Al + gA);
            cp16(base + BH_OFF + so, Bh + gB);
            cp16(base + BL_OFF + so, Bl + gB);
        }
        cp_commit();
    };

    load_stage(0, 0);

    const int arow = wm * 64 + (lane & 15);
    const int achk = lane >> 4;
    const int brow = wn * 32 + ((lane & 16) >> 1) + (lane & 7);
    const int bchk = (lane >> 3) & 1;

    for (int kt = 0; kt < KT; kt++) {
        cp_wait0();
        __syncthreads();
        if (kt + 1 < KT) load_stage((kt + 1) & 1, kt + 1);

        uint32_t sa = sb + (kt & 1) * SLOTB;
        #pragma unroll
        for (int ks = 0; ks < 2; ks++) {
            uint32_t a_h[4][4], a_l[4][4], b_h[2][4], b_l[2][4];
            #pragma unroll
            for (int mt = 0; mt < 4; mt++) {
                uint32_t ad = sa + AH_OFF + (arow + mt * 16) * ROWB + (ks * 2 + achk) * 16;
                ldsm4(a_h[mt], ad);
                ldsm4(a_l[mt], ad + (AL_OFF - AH_OFF));
            }
            #pragma unroll
            for (int p = 0; p < 2; p++) {
                uint32_t bd = sa + BH_OFF + (brow + p * 16) * ROWB + (ks * 2 + bchk) * 16;
                ldsm4(b_h[p], bd);
                ldsm4(b_l[p], bd + (BL_OFF - BH_OFF));
            }
            #pragma unroll
            for (int mt = 0; mt < 4; mt++)
                #pragma unroll
                for (int nt = 0; nt < 4; nt++)
                    mma_fp16(acc[mt][nt], a_h[mt], &b_h[nt >> 1][(nt & 1) * 2]);
            #pragma unroll
            for (int mt = 0; mt < 4; mt++)
                #pragma unroll
                for (int nt = 0; nt < 4; nt++)
                    mma_fp16(acc[mt][nt], a_h[mt], &b_l[nt >> 1][(nt & 1) * 2]);
            #pragma unroll
            for (int mt = 0; mt < 4; mt++)
                #pragma unroll
                for (int nt = 0; nt < 4; nt++)
                    mma_fp16(acc[mt][nt], a_l[mt], &b_h[nt >> 1][(nt & 1) * 2]);
        }
    }

    #pragma unroll
    for (int mt = 0; mt < 4; mt++) {
        int mr = m0 + wm * 64 + mt * 16 + (lane >> 2);
        #pragma unroll
        for (int nt = 0; nt < 4; nt++) {
            int nc = n0 + wn * 32 + nt * 8 + (lane & 3) * 2;
            size_t i0 = bz * sC + ((size_t)mr << 10) + nc;
            size_t i1 = i0 + (8 << 10);
            float v00 = acc[mt][nt][0], v01 = acc[mt][nt][1];
            float v10 = acc[mt][nt][2], v11 = acc[mt][nt][3];
            if (SPLIT_OUT) {
                __half h00 = __float2half_rn(v00), h01 = __float2half_rn(v01);
                __half h10 = __float2half_rn(v10), h11 = __float2half_rn(v11);
                *(__half2*)(Chg + i0) = __halves2half2(h00, h01);
                *(__half2*)(Chg + i1) = __halves2half2(h10, h11);
                *(__half2*)(Clg + i0) = __halves2half2(
                    __float2half_rn(v00 - __half2float(h00)),
                    __float2half_rn(v01 - __half2float(h01)));
                *(__half2*)(Clg + i1) = __halves2half2(
                    __float2half_rn(v10 - __half2float(h10)),
                    __float2half_rn(v11 - __half2float(h11)));
            } else {
                *(float2*)(Cg + i0) = make_float2(v00, v01);
                *(float2*)(Cg + i1) = make_float2(v10, v11);
            }
        }
    }

    if (STATS) {
        __syncthreads();
        float* scm = (float*)dsm;
        float* srm = (float*)(dsm + 512);

        float cmax[4][2];
        #pragma unroll
        for (int nt = 0; nt < 4; nt++)
            #pragma unroll
            for (int par = 0; par < 2; par++) {
                float m = fmaxf(acc[0][nt][par], acc[0][nt][par + 2]);
                #pragma unroll
                for (int mt = 1; mt < 4; mt++)
                    m = fmaxf(m, fmaxf(acc[mt][nt][par], acc[mt][nt][par + 2]));
                cmax[nt][par] = m;
            }
        #pragma unroll
        for (int o = 4; o <= 16; o <<= 1)
            #pragma unroll
            for (int nt = 0; nt < 4; nt++)
                #pragma unroll
                for (int par = 0; par < 2; par++)
                    cmax[nt][par] = fmaxf(cmax[nt][par],
                                          __shfl_xor_sync(0xffffffff, cmax[nt][par], o));
        if (wm == 0 && lane < 4) {
            #pragma unroll
            for (int nt = 0; nt < 4; nt++)
                #pragma unroll
                for (int par = 0; par < 2; par++)
                    scm[wn * 32 + nt * 8 + lane * 2 + par] = cmax[nt][par];
        }
        __syncthreads();
        if (wm == 1 && lane < 4) {
            #pragma unroll
            for (int nt = 0; nt < 4; nt++)
                #pragma unroll
                for (int par = 0; par < 2; par++) {
                    int c = wn * 32 + nt * 8 + lane * 2 + par;
                    scm[c] = fmaxf(scm[c], cmax[nt][par]);
                }
        }

        float rmax[4][2];
        #pragma unroll
        for (int mt = 0; mt < 4; mt++)
            #pragma unroll
            for (int qr = 0; qr < 2; qr++) {
                float m = fmaxf(acc[mt][0][qr * 2], acc[mt][0][qr * 2 + 1]);
                #pragma unroll
                for (int nt = 1; nt < 4; nt++)
                    m = fmaxf(m, fmaxf(acc[mt][nt][qr * 2], acc[mt][nt][qr * 2 + 1]));
                rmax[mt][qr] = m;
            }
        #pragma unroll
        for (int o = 1; o <= 2; o <<= 1)
            #pragma unroll
            for (int mt = 0; mt < 4; mt++)
                #pragma unroll
                for (int qr = 0; qr < 2; qr++)
                    rmax[mt][qr] = fmaxf(rmax[mt][qr],
                                         __shfl_xor_sync(0xffffffff, rmax[mt][qr], o));
        if ((lane & 3) == 0) {
            #pragma unroll
            for (int mt = 0; mt < 4; mt++)
                #pragma unroll
                for (int qr = 0; qr < 2; qr++)
                    srm[wn * 128 + wm * 64 + mt * 16 + (lane >> 2) + qr * 8] = rmax[mt][qr];
        }
        __syncthreads();

        if (tid < 128) {
            pmg[((bz << 3) + blockIdx.y) * NN + n0 + tid] = scm[tid];
            float m = fmaxf(fmaxf(srm[tid], srm[128 + tid]),
                            fmaxf(srm[256 + tid], srm[384 + tid]));
            pmrg[((bz << 3) + blockIdx.x) * NN + m0 + tid] = m;
        }
    }
}

// ---------------- single-product attention GEMM, BK=64 ----------------
#define ROWB64 144
#define A34_OFF 0
#define B34_OFF (128 * ROWB64)
#define SLOT34 (2 * 128 * ROWB64)       // 36864
#define SMEM34 (2 * SLOT34)             // 73728
#define KT34 16

__global__ __launch_bounds__(256, 2)
void gemm34_kernel(const __half* __restrict__ A3, const __half* __restrict__ B3,
                   const float* __restrict__ sc3, float* __restrict__ C3,
                   const __half* __restrict__ A4, const __half* __restrict__ B4,
                   const float* __restrict__ sc4, float* __restrict__ C4)
{
    extern __shared__ char dsm[];
    const uint32_t sb = smem_to_u32(dsm);
    const int z = blockIdx.z;
    const size_t off = (size_t)(z & 15) << 20;
    const int bn = (z & 15) * NN;
    const __half* A = (z < 16) ? A3 + off : A4 + off;
    const __half* B = (z < 16) ? B3 + off : B4 + off;
    const float* scb = ((z < 16) ? sc3 : sc4) + bn;
    float* C = ((z < 16) ? C3 : C4) + off;

    const int tid = threadIdx.x;
    const int lane = tid & 31;
    const int w = tid >> 5;
    const int wm = w & 1;
    const int wn = w >> 1;
    const int m0 = blockIdx.y * 128;
    const int n0 = blockIdx.x * 128;

    float acc[4][4][4];
    #pragma unroll
    for (int i = 0; i < 4; i++)
        #pragma unroll
        for (int j = 0; j < 4; j++)
            #pragma unroll
            for (int q = 0; q < 4; q++) acc[i][j][q] = 0.0f;

    auto load_stage = [&](int slot, int kt) {
        uint32_t base = sb + slot * SLOT34;
        int k0 = kt * 64;
        #pragma unroll
        for (int i = 0; i < 4; i++) {
            int f = tid + i * 256;
            int row = f >> 3, ch = f & 7;
            uint32_t so = row * ROWB64 + ch * 16;
            cp16(base + A34_OFF + so, A + ((size_t)(m0 + row) << 10) + k0 + ch * 8);
            cp16(base + B34_OFF + so, B + ((size_t)(n0 + row) << 10) + k0 + ch * 8);
        }
        cp_commit();
    };

    load_stage(0, 0);

    const int arow = wm * 64 + (lane & 15);
    const int achk = lane >> 4;
    const int brow = wn * 32 + ((lane & 16) >> 1) + (lane & 7);
    const int bchk = (lane >> 3) & 1;

    for (int kt = 0; kt < KT34; kt++) {
        cp_wait0();
        __syncthreads();
        if (kt + 1 < KT34) load_stage((kt + 1) & 1, kt + 1);

        uint32_t sa = sb + (kt & 1) * SLOT34;
        #pragma unroll
        for (int ks = 0; ks < 4; ks++) {
            uint32_t a_h[4][4], b_h[2][4];
            #pragma unroll
            for (int mt = 0; mt < 4; mt++)
                ldsm4(a_h[mt], sa + A34_OFF + (arow + mt * 16) * ROWB64 + (ks * 2 + achk) * 16);
            #pragma unroll
            for (int p = 0; p < 2; p++)
                ldsm4(b_h[p], sa + B34_OFF + (brow + p * 16) * ROWB64 + (ks * 2 + bchk) * 16);
            #pragma unroll
            for (int mt = 0; mt < 4; mt++)
                #pragma unroll
                for (int nt = 0; nt < 4; nt++)
                    mma_fp16(acc[mt][nt], a_h[mt], &b_h[nt >> 1][(nt & 1) * 2]);
        }
    }

    #pragma unroll
    for (int mt = 0; mt < 4; mt++) {
        int mr = m0 + wm * 64 + mt * 16 + (lane >> 2);
        float s0 = scb[mr], s1 = scb[mr + 8];
        #pragma unroll
        for (int nt = 0; nt < 4; nt++) {
            int nc = n0 + wn * 32 + nt * 8 + (lane & 3) * 2;
            size_t i0 = ((size_t)mr << 10) + nc;
            size_t i1 = i0 + (8 << 10);
            *(float2*)(C + i0) = make_float2(acc[mt][nt][0] * s0, acc[mt][nt][1] * s0);
            *(float2*)(C + i1) = make_float2(acc[mt][nt][2] * s1, acc[mt][nt][3] * s1);
        }
    }
}

// ---------------- elementwise / reduction kernels ----------------
__global__ void split2_kernel(const float* __restrict__ x1, __half* __restrict__ h1,
                              __half* __restrict__ l1,
                              const float* __restrict__ x2, __half* __restrict__ h2,
                              __half* __restrict__ l2)
{
    int bid = blockIdx.x;
    const float* x;
    __half *h, *l;
    if (bid < 16384) { x = x1; h = h1; l = l1; }
    else { x = x2; h = h2; l = l2; bid -= 16384; }
    size_t i = ((size_t)bid * 256 + threadIdx.x) * 4;
    float4 v = *(const float4*)(x + i);
    union { __half hh[4]; uint2 u; } ph, pl;
    float f[4] = {v.x, v.y, v.z, v.w};
    #pragma unroll
    for (int j = 0; j < 4; j++) {
        __half b = __float2half_rn(f[j]);
        ph.hh[j] = b;
        pl.hh[j] = __float2half_rn(f[j] - __half2float(b));
    }
    *(uint2*)(h + i) = ph.u;
    *(uint2*)(l + i) = pl.u;
}

__global__ void wtrans_kernel(const float* __restrict__ W, __half* __restrict__ h,
                              __half* __restrict__ l)
{
    __shared__ float tile[32][33];
    int e0 = blockIdx.x << 5, d0 = blockIdx.y << 5;
    int tx = threadIdx.x, ty = threadIdx.y;
    #pragma unroll
    for (int j = 0; j < 4; j++) {
        int r = ty + (j << 3);
        tile[r][tx] = W[(size_t)(d0 + r) * NN + e0 + tx];
    }
    __syncthreads();
    #pragma unroll
    for (int j = 0; j < 4; j++) {
        int r = ty + (j << 3);
        float v = tile[tx][r];
        __half hh = __float2half_rn(v);
        size_t o = (size_t)(e0 + r) * NN + d0 + tx;
        h[o] = hh;
        l[o] = __float2half_rn(v - __half2float(hh));
    }
}

// merged max reduce: z=0 -> pm->mc, z=1 -> pmr->mr
__global__ void maxred2_kernel(const float* __restrict__ pm, float* __restrict__ mc,
                               const float* __restrict__ pmr, float* __restrict__ mr)
{
    const float* src = blockIdx.z ? pmr : pm;
    float* dst = blockIdx.z ? mr : mc;
    int b = blockIdx.y;
    int t = blockIdx.x * 256 + threadIdx.x;
    float m = -INFINITY;
    #pragma unroll
    for (int c = 0; c < 8; c++) m = fmaxf(m, src[((b << 3) + c) * NN + t]);
    dst[b * NN + t] = m;
}

// one-pass softmax materialization:
// reads cc tile once; writes E_T[t][s] (transposed, col-max) and E_r[s][t]
// (straight, row-max); emits per-tile partial sums for both normalizations.
__global__ void expboth_kernel(const float* __restrict__ cc,
                               const float* __restrict__ mc, const float* __restrict__ mr,
                               __half* __restrict__ ET, __half* __restrict__ ER,
                               float* __restrict__ psc, float* __restrict__ psr)
{
    __shared__ float tile[32][33];
    int b = blockIdx.z;
    int s0 = blockIdx.x << 5, t0 = blockIdx.y << 5;
    int tx = threadIdx.x, ty = threadIdx.y;
    size_t cb = (size_t)b << 20;

    #pragma unroll
    for (int j = 0; j < 4; j++) {
        int r = ty + (j << 3);
        tile[r][tx] = cc[cb + ((size_t)(s0 + r) << 10) + t0 + tx];
    }
    __syncthreads();

    // E_T path: row r = t, lanes = s. partial col-softmax sum over the 32 s here.
    #pragma unroll
    for (int j = 0; j < 4; j++) {
        int r = ty + (j << 3);
        float m = mc[b * NN + t0 + r];
        float e = __expf(tile[tx][r] - m);
        __half h = __float2half_rn(e);
        ET[cb + ((size_t)(t0 + r) << 10) + s0 + tx] = h;
        float qs = __half2float(h);
        #pragma unroll
        for (int o = 16; o > 0; o >>= 1) qs += __shfl_xor_sync(0xffffffff, qs, o);
        if (tx == 0) psc[(size_t)blockIdx.x * (NB * NN) + b * NN + t0 + r] = qs;
    }

    // E_r path: row r = s, lanes = t. partial row-softmax sum over the 32 t here.
    #pragma unroll
    for (int j = 0; j < 4; j++) {
        int r = ty + (j << 3);
        float m = mr[b * NN + s0 + r];
        float e = __expf(tile[r][tx] - m);
        __half h = __float2half_rn(e);
        ER[cb + ((size_t)(s0 + r) << 10) + t0 + tx] = h;
        float qs = __half2float(h);
        #pragma unroll
        for (int o = 16; o > 0; o >>= 1) qs += __shfl_xor_sync(0xffffffff, qs, o);
        if (tx == 0) psr[(size_t)blockIdx.y * (NB * NN) + b * NN + s0 + r] = qs;
    }
}

// reduce 32 partial sums -> inverse; z=0 -> psc->invc, z=1 -> psr->invr
__global__ void sumred2_kernel(const float* __restrict__ psc, float* __restrict__ invc,
                               const float* __restrict__ psr, float* __restrict__ invr)
{
    const float* src = blockIdx.z ? psr : psc;
    float* dst = blockIdx.z ? invr : invc;
    int b = blockIdx.y;
    int t = blockIdx.x * 256 + threadIdx.x;
    float s = 0.0f;
    #pragma unroll
    for (int c = 0; c < 32; c++) s += src[(size_t)c * (NB * NN) + b * NN + t];
    dst[b * NN + t] = 1.0f / s;
}

// ---------------- host ----------------
extern "C" void kernel_launch(void* const* d_in, const int* in_sizes, int n_in,
                              void* d_out, int out_size)
{
    const float* f1 = (const float*)d_in[0];
    const float* f2 = (const float*)d_in[1];
    const float* W  = (const float*)d_in[2];
    float* out1 = (float*)d_out;
    float* out2 = out1 + ((size_t)NB << 20);

    __half *f1h, *f1l, *f2h, *f2l, *wth, *wtl, *a1h, *a1l, *et, *er;
    float *cc, *pm, *pmr, *psc, *psr, *mc, *mr, *invc, *invr;
    cudaGetSymbolAddress((void**)&f1h, g_f1h); cudaGetSymbolAddress((void**)&f1l, g_f1l);
    cudaGetSymbolAddress((void**)&f2h, g_f2h); cudaGetSymbolAddress((void**)&f2l, g_f2l);
    cudaGetSymbolAddress((void**)&wth, g_wth); cudaGetSymbolAddress((void**)&wtl, g_wtl);
    cudaGetSymbolAddress((void**)&a1h, g_a1h); cudaGetSymbolAddress((void**)&a1l, g_a1l);
    cudaGetSymbolAddress((void**)&et, g_et);   cudaGetSymbolAddress((void**)&er, g_er);
    cudaGetSymbolAddress((void**)&cc, g_cc);
    cudaGetSymbolAddress((void**)&pm, g_pmax); cudaGetSymbolAddress((void**)&pmr, g_pmaxr);
    cudaGetSymbolAddress((void**)&psc, g_psc); cudaGetSymbolAddress((void**)&psr, g_psr);
    cudaGetSymbolAddress((void**)&mc, g_mc);   cudaGetSymbolAddress((void**)&mr, g_mr);
    cudaGetSymbolAddress((void**)&invc, g_invc);
    cudaGetSymbolAddress((void**)&invr, g_invr);

    cudaFuncSetAttribute(gemm_kernel<true,  false>, cudaFuncAttributeMaxDynamicSharedMemorySize, SMEM_DYN);
    cudaFuncSetAttribute(gemm_kernel<false, true>,  cudaFuncAttributeMaxDynamicSharedMemorySize, SMEM_DYN);
    cudaFuncSetAttribute(gemm34_kernel, cudaFuncAttributeMaxDynamicSharedMemorySize, SMEM34);

    const size_t MBe = (size_t)1 << 20;
    dim3 gg(8, 8, NB);       // logit GEMMs: 1024 CTAs
    dim3 gg34(8, 8, 2 * NB); // fused attention GEMMs: 2048 CTAs

    // fp16 splits (merged f1+f2) + W transpose split
    split2_kernel<<<32768, 256>>>(f1, f1h, f1l, f2, f2h, f2l);
    wtrans_kernel<<<dim3(32, 32), dim3(32, 8)>>>(W, wth, wtl);

    // 1. a1 = f1 @ W (3-product) -> fp16 split
    gemm_kernel<true,  false><<<gg, 256, SMEM_DYN>>>(f1h, f1l, wth, wtl,
                                                     nullptr, a1h, a1l,
                                                     nullptr, nullptr, MBe, 0, MBe);
    // 2. cc = a1 @ f2^T (3-product) -> fp32, fused partial row/col maxes
    gemm_kernel<false, true><<<gg, 256, SMEM_DYN>>>(a1h, a1l, f2h, f2l,
                                                    cc, nullptr, nullptr,
                                                    pm, pmr, MBe, MBe, MBe);
    // 3. reduce partial maxes -> mc, mr (one launch)
    maxred2_kernel<<<dim3(4, NB, 2), 256>>>(pm, mc, pmr, mr);
    // 4. one-pass E_T + E_r + partial sums
    expboth_kernel<<<dim3(32, 32, NB), dim3(32, 8)>>>(cc, mc, mr, et, er, psc, psr);
    // 5. reduce partial sums -> invc, invr (one launch)
    sumred2_kernel<<<dim3(4, NB, 2), 256>>>(psc, invc, psr, invr);
    // 6. fused attention GEMMs, single product, BK=64
    gemm34_kernel<<<gg34, 256, SMEM34>>>(et, f1h, invc, out1,
                                         er, f2h, invr, out2);
}

// round 15
// speedup vs baseline: 1.6235x; 1.0075x over previous
#include <cuda_runtime.h>
#include <cuda_fp16.h>
#include <math.h>
#include <stdint.h>

#define NB 16
#define NN 1024

// ---------------- helpers ----------------
__device__ __forceinline__ uint32_t smem_to_u32(const void* p) {
    uint32_t a;
    asm("{ .reg .u64 t; cvta.to.shared.u64 t, %1; cvt.u32.u64 %0, t; }" : "=r"(a) : "l"(p));
    return a;
}
__device__ __forceinline__ void cp16(uint32_t dst, const void* src) {
    asm volatile("cp.async.cg.shared.global [%0], [%1], 16;" :: "r"(dst), "l"(src));
}
__device__ __forceinline__ void cp_commit() { asm volatile("cp.async.commit_group;" ::: "memory"); }
__device__ __forceinline__ void cp_wait0()  { asm volatile("cp.async.wait_group 0;" ::: "memory"); }

__device__ __forceinline__ void ldsm4(uint32_t* r, uint32_t addr) {
    asm volatile("ldmatrix.sync.aligned.m8n8.x4.shared.b16 {%0,%1,%2,%3}, [%4];"
                 : "=r"(r[0]), "=r"(r[1]), "=r"(r[2]), "=r"(r[3]) : "r"(addr));
}
__device__ __forceinline__ void mma_fp16(float* c, const uint32_t* a, const uint32_t* b) {
    asm volatile(
        "mma.sync.aligned.m16n8k16.row.col.f32.f16.f16.f32 "
        "{%0,%1,%2,%3}, {%4,%5,%6,%7}, {%8,%9}, {%0,%1,%2,%3};"
        : "+f"(c[0]), "+f"(c[1]), "+f"(c[2]), "+f"(c[3])
        : "r"(a[0]), "r"(a[1]), "r"(a[2]), "r"(a[3]), "r"(b[0]), "r"(b[1]));
}

// ---------------- scratch (device globals) ----------------
#define TOT ((size_t)NB * NN * NN)
__device__ __half g_f1h[TOT], g_f1l[TOT];
__device__ __half g_f2h[TOT], g_f2l[TOT];
__device__ __half g_wth[NN * NN], g_wtl[NN * NN];
__device__ __half g_a1h[TOT], g_a1l[TOT];
__device__ __half g_et[TOT];               // E_T (single fp16)
__device__ __half g_er[TOT];               // E_r (single fp16)
__device__ float g_cc[TOT];
__device__ float g_pmax[NB * 8 * NN];      // partial col maxes (GEMM2 epilogue)
__device__ float g_pmaxr[NB * 8 * NN];     // partial row maxes (GEMM2 epilogue)
__device__ float g_psc[16 * NB * NN];      // partial col-softmax sums (expboth)
__device__ float g_psr[32 * NB * NN];      // partial row-softmax sums (expboth)
__device__ float g_mc[NB * NN], g_mr[NB * NN], g_invc[NB * NN], g_invr[NB * NN];

// ---------------- fp16 logit GEMM (proven layout) ----------------
#define BK 32
#define ROWB 80
#define AH_OFF 0
#define AL_OFF (128 * ROWB)
#define BH_OFF (2 * 128 * ROWB)
#define BL_OFF (3 * 128 * ROWB)
#define SLOTB (4 * 128 * ROWB)          // 40960
#define SMEM_DYN (2 * SLOTB)            // 81920 -> 2 CTAs/SM
#define KT 32

template<bool SPLIT_OUT, bool STATS>
__global__ __launch_bounds__(256, 2)
void gemm_kernel(const __half* __restrict__ Ahg, const __half* __restrict__ Alg,
                 const __half* __restrict__ Bhg, const __half* __restrict__ Blg,
                 float* __restrict__ Cg, __half* __restrict__ Chg, __half* __restrict__ Clg,
                 float* __restrict__ pmg, float* __restrict__ pmrg,
                 size_t sA, size_t sB, size_t sC)
{
    extern __shared__ char dsm[];
    const uint32_t sb = smem_to_u32(dsm);
    const size_t bz = blockIdx.z;
    const __half* Ah = Ahg + bz * sA;
    const __half* Al = Alg + bz * sA;
    const __half* Bh = Bhg + bz * sB;
    const __half* Bl = Blg + bz * sB;

    const int tid = threadIdx.x;
    const int lane = tid & 31;
    const int w = tid >> 5;
    const int wm = w & 1;
    const int wn = w >> 1;
    const int m0 = blockIdx.y * 128;
    const int n0 = blockIdx.x * 128;

    float acc[4][4][4];
    #pragma unroll
    for (int i = 0; i < 4; i++)
        #pragma unroll
        for (int j = 0; j < 4; j++)
            #pragma unroll
            for (int q = 0; q < 4; q++) acc[i][j][q] = 0.0f;

    auto load_stage = [&](int slot, int kt) {
        uint32_t base = sb + slot * SLOTB;
        int k0 = kt * BK;
        #pragma unroll
        for (int i = 0; i < 2; i++) {
            int f = tid + i * 256;
            int row = f >> 2, ch = f & 3;
            uint32_t so = row * ROWB + ch * 16;
            size_t gA = ((size_t)(m0 + row) << 10) + k0 + ch * 8;
            size_t gB = ((size_t)(n0 + row) << 10) + k0 + ch * 8;
            cp16(base + AH_OFF + so, Ah + gA);
            cp16(base + AL_OFF + so, Al + gA);
            cp16(base + BH_OFF + so, Bh + gB);
            cp16(base + BL_OFF + so, Bl + gB);
        }
        cp_commit();
    };

    load_stage(0, 0);

    const int arow = wm * 64 + (lane & 15);
    const int achk = lane >> 4;
    const int brow = wn * 32 + ((lane & 16) >> 1) + (lane & 7);
    const int bchk = (lane >> 3) & 1;

    for (int kt = 0; kt < KT; kt++) {
        cp_wait0();
        __syncthreads();
        if (kt + 1 < KT) load_stage((kt + 1) & 1, kt + 1);

        uint32_t sa = sb + (kt & 1) * SLOTB;
        #pragma unroll
        for (int ks = 0; ks < 2; ks++) {
            uint32_t a_h[4][4], a_l[4][4], b_h[2][4], b_l[2][4];
            #pragma unroll
            for (int mt = 0; mt < 4; mt++) {
                uint32_t ad = sa + AH_OFF + (arow + mt * 16) * ROWB + (ks * 2 + achk) * 16;
                ldsm4(a_h[mt], ad);
                ldsm4(a_l[mt], ad + (AL_OFF - AH_OFF));
            }
            #pragma unroll
            for (int p = 0; p < 2; p++) {
                uint32_t bd = sa + BH_OFF + (brow + p * 16) * ROWB + (ks * 2 + bchk) * 16;
                ldsm4(b_h[p], bd);
                ldsm4(b_l[p], bd + (BL_OFF - BH_OFF));
            }
            #pragma unroll
            for (int mt = 0; mt < 4; mt++)
                #pragma unroll
                for (int nt = 0; nt < 4; nt++)
                    mma_fp16(acc[mt][nt], a_h[mt], &b_h[nt >> 1][(nt & 1) * 2]);
            #pragma unroll
            for (int mt = 0; mt < 4; mt++)
                #pragma unroll
                for (int nt = 0; nt < 4; nt++)
                    mma_fp16(acc[mt][nt], a_h[mt], &b_l[nt >> 1][(nt & 1) * 2]);
            #pragma unroll
            for (int mt = 0; mt < 4; mt++)
                #pragma unroll
                for (int nt = 0; nt < 4; nt++)
                    mma_fp16(acc[mt][nt], a_l[mt], &b_h[nt >> 1][(nt & 1) * 2]);
        }
    }

    #pragma unroll
    for (int mt = 0; mt < 4; mt++) {
        int mr = m0 + wm * 64 + mt * 16 + (lane >> 2);
        #pragma unroll
        for (int nt = 0; nt < 4; nt++) {
            int nc = n0 + wn * 32 + nt * 8 + (lane & 3) * 2;
            size_t i0 = bz * sC + ((size_t)mr << 10) + nc;
            size_t i1 = i0 + (8 << 10);
            float v00 = acc[mt][nt][0], v01 = acc[mt][nt][1];
            float v10 = acc[mt][nt][2], v11 = acc[mt][nt][3];
            if (SPLIT_OUT) {
                __half h00 = __float2half_rn(v00), h01 = __float2half_rn(v01);
                __half h10 = __float2half_rn(v10), h11 = __float2half_rn(v11);
                *(__half2*)(Chg + i0) = __halves2half2(h00, h01);
                *(__half2*)(Chg + i1) = __halves2half2(h10, h11);
                *(__half2*)(Clg + i0) = __halves2half2(
                    __float2half_rn(v00 - __half2float(h00)),
                    __float2half_rn(v01 - __half2float(h01)));
                *(__half2*)(Clg + i1) = __halves2half2(
                    __float2half_rn(v10 - __half2float(h10)),
                    __float2half_rn(v11 - __half2float(h11)));
            } else {
                *(float2*)(Cg + i0) = make_float2(v00, v01);
                *(float2*)(Cg + i1) = make_float2(v10, v11);
            }
        }
    }

    if (STATS) {
        __syncthreads();
        float* scm = (float*)dsm;
        float* srm = (float*)(dsm + 512);

        float cmax[4][2];
        #pragma unroll
        for (int nt = 0; nt < 4; nt++)
            #pragma unroll
            for (int par = 0; par < 2; par++) {
                float m = fmaxf(acc[0][nt][par], acc[0][nt][par + 2]);
                #pragma unroll
                for (int mt = 1; mt < 4; mt++)
                    m = fmaxf(m, fmaxf(acc[mt][nt][par], acc[mt][nt][par + 2]));
                cmax[nt][par] = m;
            }
        #pragma unroll
        for (int o = 4; o <= 16; o <<= 1)
            #pragma unroll
            for (int nt = 0; nt < 4; nt++)
                #pragma unroll
                for (int par = 0; par < 2; par++)
                    cmax[nt][par] = fmaxf(cmax[nt][par],
                                          __shfl_xor_sync(0xffffffff, cmax[nt][par], o));
        if (wm == 0 && lane < 4) {
            #pragma unroll
            for (int nt = 0; nt < 4; nt++)
                #pragma unroll
                for (int par = 0; par < 2; par++)
                    scm[wn * 32 + nt * 8 + lane * 2 + par] = cmax[nt][par];
        }
        __syncthreads();
        if (wm == 1 && lane < 4) {
            #pragma unroll
            for (int nt = 0; nt < 4; nt++)
                #pragma unroll
                for (int par = 0; par < 2; par++) {
                    int c = wn * 32 + nt * 8 + lane * 2 + par;
                    scm[c] = fmaxf(scm[c], cmax[nt][par]);
                }
        }

        float rmax[4][2];
        #pragma unroll
        for (int mt = 0; mt < 4; mt++)
            #pragma unroll
            for (int qr = 0; qr < 2; qr++) {
                float m = fmaxf(acc[mt][0][qr * 2], acc[mt][0][qr * 2 + 1]);
                #pragma unroll
                for (int nt = 1; nt < 4; nt++)
                    m = fmaxf(m, fmaxf(acc[mt][nt][qr * 2], acc[mt][nt][qr * 2 + 1]));
                rmax[mt][qr] = m;
            }
        #pragma unroll
        for (int o = 1; o <= 2; o <<= 1)
            #pragma unroll
            for (int mt = 0; mt < 4; mt++)
                #pragma unroll
                for (int qr = 0; qr < 2; qr++)
                    rmax[mt][qr] = fmaxf(rmax[mt][qr],
                                         __shfl_xor_sync(0xffffffff, rmax[mt][qr], o));
        if ((lane & 3) == 0) {
            #pragma unroll
            for (int mt = 0; mt < 4; mt++)
                #pragma unroll
                for (int qr = 0; qr < 2; qr++)
                    srm[wn * 128 + wm * 64 + mt * 16 + (lane >> 2) + qr * 8] = rmax[mt][qr];
        }
        __syncthreads();

        if (tid < 128) {
            pmg[((bz << 3) + blockIdx.y) * NN + n0 + tid] = scm[tid];
            float m = fmaxf(fmaxf(srm[tid], srm[128 + tid]),
                            fmaxf(srm[256 + tid], srm[384 + tid]));
            pmrg[((bz << 3) + blockIdx.x) * NN + m0 + tid] = m;
        }
    }
}

// ---------------- single-product attention GEMM, BK=64 ----------------
#define ROWB64 144
#define A34_OFF 0
#define B34_OFF (128 * ROWB64)
#define SLOT34 (2 * 128 * ROWB64)       // 36864
#define SMEM34 (2 * SLOT34)             // 73728
#define KT34 16

__global__ __launch_bounds__(256, 2)
void gemm34_kernel(const __half* __restrict__ A3, const __half* __restrict__ B3,
                   const float* __restrict__ sc3, float* __restrict__ C3,
                   const __half* __restrict__ A4, const __half* __restrict__ B4,
                   const float* __restrict__ sc4, float* __restrict__ C4)
{
    extern __shared__ char dsm[];
    const uint32_t sb = smem_to_u32(dsm);
    const int z = blockIdx.z;
    const size_t off = (size_t)(z & 15) << 20;
    const int bn = (z & 15) * NN;
    const __half* A = (z < 16) ? A3 + off : A4 + off;
    const __half* B = (z < 16) ? B3 + off : B4 + off;
    const float* scb = ((z < 16) ? sc3 : sc4) + bn;
    float* C = ((z < 16) ? C3 : C4) + off;

    const int tid = threadIdx.x;
    const int lane = tid & 31;
    const int w = tid >> 5;
    const int wm = w & 1;
    const int wn = w >> 1;
    const int m0 = blockIdx.y * 128;
    const int n0 = blockIdx.x * 128;

    float acc[4][4][4];
    #pragma unroll
    for (int i = 0; i < 4; i++)
        #pragma unroll
        for (int j = 0; j < 4; j++)
            #pragma unroll
            for (int q = 0; q < 4; q++) acc[i][j][q] = 0.0f;

    auto load_stage = [&](int slot, int kt) {
        uint32_t base = sb + slot * SLOT34;
        int k0 = kt * 64;
        #pragma unroll
        for (int i = 0; i < 4; i++) {
            int f = tid + i * 256;
            int row = f >> 3, ch = f & 7;
            uint32_t so = row * ROWB64 + ch * 16;
            cp16(base + A34_OFF + so, A + ((size_t)(m0 + row) << 10) + k0 + ch * 8);
            cp16(base + B34_OFF + so, B + ((size_t)(n0 + row) << 10) + k0 + ch * 8);
        }
        cp_commit();
    };

    load_stage(0, 0);

    const int arow = wm * 64 + (lane & 15);
    const int achk = lane >> 4;
    const int brow = wn * 32 + ((lane & 16) >> 1) + (lane & 7);
    const int bchk = (lane >> 3) & 1;

    for (int kt = 0; kt < KT34; kt++) {
        cp_wait0();
        __syncthreads();
        if (kt + 1 < KT34) load_stage((kt + 1) & 1, kt + 1);

        uint32_t sa = sb + (kt & 1) * SLOT34;
        #pragma unroll
        for (int ks = 0; ks < 4; ks++) {
            uint32_t a_h[4][4], b_h[2][4];
            #pragma unroll
            for (int mt = 0; mt < 4; mt++)
                ldsm4(a_h[mt], sa + A34_OFF + (arow + mt * 16) * ROWB64 + (ks * 2 + achk) * 16);
            #pragma unroll
            for (int p = 0; p < 2; p++)
                ldsm4(b_h[p], sa + B34_OFF + (brow + p * 16) * ROWB64 + (ks * 2 + bchk) * 16);
            #pragma unroll
            for (int mt = 0; mt < 4; mt++)
                #pragma unroll
                for (int nt = 0; nt < 4; nt++)
                    mma_fp16(acc[mt][nt], a_h[mt], &b_h[nt >> 1][(nt & 1) * 2]);
        }
    }

    #pragma unroll
    for (int mt = 0; mt < 4; mt++) {
        int mr = m0 + wm * 64 + mt * 16 + (lane >> 2);
        float s0 = scb[mr], s1 = scb[mr + 8];
        #pragma unroll
        for (int nt = 0; nt < 4; nt++) {
            int nc = n0 + wn * 32 + nt * 8 + (lane & 3) * 2;
            size_t i0 = ((size_t)mr << 10) + nc;
            size_t i1 = i0 + (8 << 10);
            *(float2*)(C + i0) = make_float2(acc[mt][nt][0] * s0, acc[mt][nt][1] * s0);
            *(float2*)(C + i1) = make_float2(acc[mt][nt][2] * s1, acc[mt][nt][3] * s1);
        }
    }
}

// ---------------- fused input transform: f1 split | f2 split | W^T split ----------------
__global__ void transform_kernel(const float* __restrict__ f1, __half* __restrict__ f1h,
                                 __half* __restrict__ f1l,
                                 const float* __restrict__ f2, __half* __restrict__ f2h,
                                 __half* __restrict__ f2l,
                                 const float* __restrict__ W, __half* __restrict__ wth,
                                 __half* __restrict__ wtl)
{
    __shared__ float tile[32][33];
    int bid = blockIdx.x;
    if (bid < 32768) {
        const float* x;
        __half *h, *l;
        if (bid < 16384) { x = f1; h = f1h; l = f1l; }
        else { x = f2; h = f2h; l = f2l; bid -= 16384; }
        size_t i = ((size_t)bid * 256 + threadIdx.x) * 4;
        float4 v = *(const float4*)(x + i);
        union { __half hh[4]; uint2 u; } ph, pl;
        float f[4] = {v.x, v.y, v.z, v.w};
        #pragma unroll
        for (int j = 0; j < 4; j++) {
            __half b = __float2half_rn(f[j]);
            ph.hh[j] = b;
            pl.hh[j] = __float2half_rn(f[j] - __half2float(b));
        }
        *(uint2*)(h + i) = ph.u;
        *(uint2*)(l + i) = pl.u;
    } else {
        int r = bid - 32768;                    // 0..1023
        int e0 = (r & 31) << 5, d0 = (r >> 5) << 5;
        int tx = threadIdx.x & 31, ty = threadIdx.x >> 5;
        #pragma unroll
        for (int j = 0; j < 4; j++) {
            int rr = ty + (j << 3);
            tile[rr][tx] = W[(size_t)(d0 + rr) * NN + e0 + tx];
        }
        __syncthreads();
        #pragma unroll
        for (int j = 0; j < 4; j++) {
            int rr = ty + (j << 3);
            float v = tile[tx][rr];
            __half hh = __float2half_rn(v);
            size_t o = (size_t)(e0 + rr) * NN + d0 + tx;
            wth[o] = hh;
            wtl[o] = __float2half_rn(v - __half2float(hh));
        }
    }
}

// merged max reduce: z=0 -> pm->mc, z=1 -> pmr->mr
__global__ void maxred2_kernel(const float* __restrict__ pm, float* __restrict__ mc,
                               const float* __restrict__ pmr, float* __restrict__ mr)
{
    const float* src = blockIdx.z ? pmr : pm;
    float* dst = blockIdx.z ? mr : mc;
    int b = blockIdx.y;
    int t = blockIdx.x * 256 + threadIdx.x;
    float m = -INFINITY;
    #pragma unroll
    for (int c = 0; c < 8; c++) m = fmaxf(m, src[((b << 3) + c) * NN + t]);
    dst[b * NN + t] = m;
}

// one-pass softmax materialization, 64(s) x 32(t) tiles.
// E_T writes become half2 -> 128B/warp segments.
__global__ void expboth_kernel(const float* __restrict__ cc,
                               const float* __restrict__ mc, const float* __restrict__ mr,
                               __half* __restrict__ ET, __half* __restrict__ ER,
                               float* __restrict__ psc, float* __restrict__ psr)
{
    __shared__ float tile[32][73];              // [t][s], odd stride -> conflict-free
    int b = blockIdx.z;
    int s0 = blockIdx.x << 6, t0 = blockIdx.y << 5;
    int tx = threadIdx.x, ty = threadIdx.y;     // (32, 8)
    size_t cb = (size_t)b << 20;

    #pragma unroll
    for (int j = 0; j < 8; j++) {
        int sl = ty + (j << 3);                 // 0..63
        tile[tx][sl] = cc[cb + ((size_t)(s0 + sl) << 10) + t0 + tx];
    }
    __syncthreads();

    // E_T path: row r = t; each lane covers s = 2tx, 2tx+1 -> half2 write (128B/warp)
    #pragma unroll
    for (int j = 0; j < 4; j++) {
        int r = ty + (j << 3);
        float m = mc[b * NN + t0 + r];
        float e0 = __expf(tile[r][2 * tx] - m);
        float e1 = __expf(tile[r][2 * tx + 1] - m);
        __half h0 = __float2half_rn(e0), h1 = __float2half_rn(e1);
        *(__half2*)(ET + cb + ((size_t)(t0 + r) << 10) + s0 + 2 * tx) = __halves2half2(h0, h1);
        float qs = __half2float(h0) + __half2float(h1);
        #pragma unroll
        for (int o = 16; o > 0; o >>= 1) qs += __shfl_xor_sync(0xffffffff, qs, o);
        if (tx == 0) psc[(size_t)blockIdx.x * (NB * NN) + b * NN + t0 + r] = qs;
    }

    // E_r path: row sl = s; lanes = t
    #pragma unroll
    for (int j = 0; j < 8; j++) {
        int sl = ty + (j << 3);
        float m = mr[b * NN + s0 + sl];
        float e = __expf(tile[tx][sl] - m);
        __half h = __float2half_rn(e);
        ER[cb + ((size_t)(s0 + sl) << 10) + t0 + tx] = h;
        float qs = __half2float(h);
        #pragma unroll
        for (int o = 16; o > 0; o >>= 1) qs += __shfl_xor_sync(0xffffffff, qs, o);
        if (tx == 0) psr[(size_t)blockIdx.y * (NB * NN) + b * NN + s0 + sl] = qs;
    }
}

// reduce partial sums -> inverse; z=0 -> psc (16 partials), z=1 -> psr (32 partials)
__global__ void sumred2_kernel(const float* __restrict__ psc, float* __restrict__ invc,
                               const float* __restrict__ psr, float* __restrict__ invr)
{
    int b = blockIdx.y;
    int t = blockIdx.x * 256 + threadIdx.x;
    float s = 0.0f;
    if (blockIdx.z == 0) {
        #pragma unroll
        for (int c = 0; c < 16; c++) s += psc[(size_t)c * (NB * NN) + b * NN + t];
        invc[b * NN + t] = 1.0f / s;
    } else {
        #pragma unroll
        for (int c = 0; c < 32; c++) s += psr[(size_t)c * (NB * NN) + b * NN + t];
        invr[b * NN + t] = 1.0f / s;
    }
}

// ---------------- host ----------------
extern "C" void kernel_launch(void* const* d_in, const int* in_sizes, int n_in,
                              void* d_out, int out_size)
{
    const float* f1 = (const float*)d_in[0];
    const float* f2 = (const float*)d_in[1];
    const float* W  = (const float*)d_in[2];
    float* out1 = (float*)d_out;
    float* out2 = out1 + ((size_t)NB << 20);

    __half *f1h, *f1l, *f2h, *f2l, *wth, *wtl, *a1h, *a1l, *et, *er;
    float *cc, *pm, *pmr, *psc, *psr, *mc, *mr, *invc, *invr;
    cudaGetSymbolAddress((void**)&f1h, g_f1h); cudaGetSymbolAddress((void**)&f1l, g_f1l);
    cudaGetSymbolAddress((void**)&f2h, g_f2h); cudaGetSymbolAddress((void**)&f2l, g_f2l);
    cudaGetSymbolAddress((void**)&wth, g_wth); cudaGetSymbolAddress((void**)&wtl, g_wtl);
    cudaGetSymbolAddress((void**)&a1h, g_a1h); cudaGetSymbolAddress((void**)&a1l, g_a1l);
    cudaGetSymbolAddress((void**)&et, g_et);   cudaGetSymbolAddress((void**)&er, g_er);
    cudaGetSymbolAddress((void**)&cc, g_cc);
    cudaGetSymbolAddress((void**)&pm, g_pmax); cudaGetSymbolAddress((void**)&pmr, g_pmaxr);
    cudaGetSymbolAddress((void**)&psc, g_psc); cudaGetSymbolAddress((void**)&psr, g_psr);
    cudaGetSymbolAddress((void**)&mc, g_mc);   cudaGetSymbolAddress((void**)&mr, g_mr);
    cudaGetSymbolAddress((void**)&invc, g_invc);
    cudaGetSymbolAddress((void**)&invr, g_invr);

    cudaFuncSetAttribute(gemm_kernel<true,  false>, cudaFuncAttributeMaxDynamicSharedMemorySize, SMEM_DYN);
    cudaFuncSetAttribute(gemm_kernel<false, true>,  cudaFuncAttributeMaxDynamicSharedMemorySize, SMEM_DYN);
    cudaFuncSetAttribute(gemm34_kernel, cudaFuncAttributeMaxDynamicSharedMemorySize, SMEM34);

    const size_t MBe = (size_t)1 << 20;
    dim3 gg(8, 8, NB);       // logit GEMMs: 1024 CTAs
    dim3 gg34(8, 8, 2 * NB); // fused attention GEMMs: 2048 CTAs

    // fused input transforms (f1 split + f2 split + W^T split) — one launch
    transform_kernel<<<32768 + 1024, 256>>>(f1, f1h, f1l, f2, f2h, f2l, W, wth, wtl);

    // 1. a1 = f1 @ W (3-product) -> fp16 split
    gemm_kernel<true,  false><<<gg, 256, SMEM_DYN>>>(f1h, f1l, wth, wtl,
                                                     nullptr, a1h, a1l,
                                                     nullptr, nullptr, MBe, 0, MBe);
    // 2. cc = a1 @ f2^T (3-product) -> fp32, fused partial row/col maxes
    gemm_kernel<false, true><<<gg, 256, SMEM_DYN>>>(a1h, a1l, f2h, f2l,
                                                    cc, nullptr, nullptr,
                                                    pm, pmr, MBe, MBe, MBe);
    // 3. reduce partial maxes -> mc, mr (one launch)
    maxred2_kernel<<<dim3(4, NB, 2), 256>>>(pm, mc, pmr, mr);
    // 4. one-pass E_T + E_r + partial sums (64-wide s tiles)
    expboth_kernel<<<dim3(16, 32, NB), dim3(32, 8)>>>(cc, mc, mr, et, er, psc, psr);
    // 5. reduce partial sums -> invc, invr (one launch)
    sumred2_kernel<<<dim3(4, NB, 2), 256>>>(psc, invc, psr, invr);
    // 6. fused attention GEMMs, single product, BK=64
    gemm34_kernel<<<gg34, 256, SMEM34>>>(et, f1h, invc, out1,
                                         er, f2h, invr, out2);
}